// round 2
// baseline (speedup 1.0000x reference)
#include <cuda_runtime.h>
#include <math.h>
#include <stdint.h>

// ---------------------------------------------------------------------------
// ChannelAttentionLayer: Q=BN(conv3x3(x)), K=BN(conv1x1(x,pad1)), V likewise,
// scores = K^T Q (over channels), softmax over keys, out = V @ attn.
// Border trick: all 260 padded key positions per image share ONE key/value
// vector (conv of zeros = bias), so attention = 4096 interior keys + one
// border key with multiplicity 260.
// ---------------------------------------------------------------------------

#define NB   4
#define NC   256
#define NPIX 4096          // 64*64
#define KR   2304          // 256*9
#define NKC  32            // k-chunks of 128 in softmax reduction

// ---- static device scratch (no allocations allowed) ----
__device__ float g_xpad[(size_t)NB*NC*66*66];
__device__ float g_col [(size_t)NB*KR*NPIX];
__device__ float g_wqt [KR*NC];
__device__ float g_wkt [NC*NC];
__device__ float g_wvt [NC*NC];
__device__ float g_qc  [(size_t)NB*NC*NPIX];
__device__ float g_kc  [(size_t)NB*NC*NPIX];
__device__ float g_vc  [(size_t)NB*NC*NPIX];
__device__ float g_vt  [(size_t)NB*NPIX*NC];
__device__ float g_S   [(size_t)NB*NPIX*NPIX];   // 268 MB scores / exp buffer
__device__ float g_pred[(size_t)NB*NKC*NPIX];    // partial max / partial sum
__device__ float g_sb  [NB*NPIX];
__device__ float g_m   [NB*NPIX];
__device__ float g_iz  [NB*NPIX];
__device__ float g_bw  [NB*NPIX];
__device__ float g_a   [3*NC];
__device__ float g_dd  [3*NC];
__device__ float g_kbv [NC];
__device__ float g_vbv [NC];

// ---- fast exp: FFMA-only (no MUFU), rel err ~2.4e-6, exact enough for 1e-3 gate
__device__ __forceinline__ float fexp(float x) {
    x = fmaxf(x, -87.0f);
    float t = fmaf(x, 1.4426950408889634f, 12582912.0f);
    float i = t - 12582912.0f;                 // nearest int to x*log2e
    float f = fmaf(x, 1.4426950408889634f, -i);
    float y = f * 0.6931471805599453f;         // |y| <= 0.3466
    float p = fmaf(y, 0.0083333338f, 0.041666668f);
    p = fmaf(y, p, 0.16666667f);
    p = fmaf(y, p, 0.5f);
    p = fmaf(y, p, 1.0f);
    p = fmaf(y, p, 1.0f);
    int e = (int)i;
    return p * __int_as_float((e + 127) << 23);
}

// ---- zero-pad x into 66x66 grid ----
__global__ void pad_x(const float* __restrict__ x) {
    int idx = blockIdx.x * 256 + threadIdx.x;
    if (idx >= NB * NC * 66 * 66) return;
    int xx = idx % 66, yy = (idx / 66) % 66, bc = idx / (66 * 66);
    float v = 0.f;
    if (yy >= 1 && yy <= 64 && xx >= 1 && xx <= 64)
        v = x[(size_t)bc * NPIX + (yy - 1) * 64 + (xx - 1)];
    g_xpad[idx] = v;
}

// ---- weight transpose: wt[r*M+m] = w[m*K+r] ----
__global__ void wtrans(const float* __restrict__ w, float* __restrict__ wt, int M, int K) {
    int idx = blockIdx.x * 256 + threadIdx.x;
    if (idx >= M * K) return;
    int m = idx % M, r = idx / M;
    wt[idx] = w[(size_t)m * K + r];
}

// ---- im2col: col[b][ci*9+t][y*64+x] = xpad[b][ci][y+dy][x+dx] ----
__global__ void im2col_k() {
    size_t idx = (size_t)blockIdx.x * 256 + threadIdx.x;   // total NB*KR*NPIX
    int n = (int)(idx & 4095);
    size_t t1 = idx >> 12;
    int r = (int)(t1 % KR);
    int b = (int)(t1 / KR);
    int ci = r / 9, tt = r % 9, dy = tt / 3, dx = tt % 3;
    int y = n >> 6, xx = n & 63;
    g_col[idx] = g_xpad[(((size_t)(b * NC + ci)) * 66 + y + dy) * 66 + xx + dx];
}

// ---------------------------------------------------------------------------
// TN GEMM: C[m][n] = sum_r A[r][m] * B[r][n]   (A,B row-major over r)
// MODE 0: +bias[m]   MODE 1: raw   MODE 2: *invZ[n] + bw[n]*vbv[m]
// 128x128 tile, BK=16, 256 threads, 8x8 micro-tile, float4 everywhere.
// ---------------------------------------------------------------------------
template <int MODE>
__global__ __launch_bounds__(256, 2) void gemm_tn(
    const float* __restrict__ A, const float* __restrict__ B, float* __restrict__ C,
    int M, int N, int K, size_t sA, size_t sB, size_t sC,
    const float* __restrict__ bias, const float* __restrict__ invZ,
    const float* __restrict__ bw, const float* __restrict__ vbv)
{
    int bz = blockIdx.z;
    A += sA * bz; B += sB * bz; C += sC * bz;
    __shared__ float As[16][128];
    __shared__ float Bs[16][128];
    int tid = threadIdx.x;
    int m0 = blockIdx.y * 128, n0 = blockIdx.x * 128;
    int lr = tid >> 5, lc = (tid & 31) << 2;
    const float* Ag = A + (size_t)lr * M + m0 + lc;
    const float* Bg = B + (size_t)lr * N + n0 + lc;
    int ra = (tid >> 4) * 4, cb = (tid & 15) * 4;

    float acc[8][8];
#pragma unroll
    for (int i = 0; i < 8; i++)
#pragma unroll
        for (int j = 0; j < 8; j++) acc[i][j] = 0.f;

    for (int k0 = 0; k0 < K; k0 += 16) {
        float4 a0 = *(const float4*)Ag;
        float4 a1 = *(const float4*)(Ag + (size_t)8 * M);
        float4 b0 = *(const float4*)Bg;
        float4 b1 = *(const float4*)(Bg + (size_t)8 * N);
        __syncthreads();
        *(float4*)&As[lr][lc] = a0;  *(float4*)&As[lr + 8][lc] = a1;
        *(float4*)&Bs[lr][lc] = b0;  *(float4*)&Bs[lr + 8][lc] = b1;
        __syncthreads();
#pragma unroll
        for (int kk = 0; kk < 16; kk++) {
            float av[8], bv[8];
            *(float4*)&av[0] = *(float4*)&As[kk][ra];
            *(float4*)&av[4] = *(float4*)&As[kk][ra + 64];
            *(float4*)&bv[0] = *(float4*)&Bs[kk][cb];
            *(float4*)&bv[4] = *(float4*)&Bs[kk][cb + 64];
#pragma unroll
            for (int i = 0; i < 8; i++)
#pragma unroll
                for (int j = 0; j < 8; j++)
                    acc[i][j] = fmaf(av[i], bv[j], acc[i][j]);
        }
        Ag += (size_t)16 * M;
        Bg += (size_t)16 * N;
    }

    const float* izp = (MODE == 2) ? invZ + (size_t)bz * N : (const float*)0;
    const float* bwp = (MODE == 2) ? bw   + (size_t)bz * N : (const float*)0;
#pragma unroll
    for (int i = 0; i < 8; i++) {
        int row = m0 + ra + (i & 3) + ((i >> 2) << 6);
        float bi = (MODE == 0) ? bias[row] : 0.f;
        float vb = (MODE == 2) ? vbv[row] : 0.f;
#pragma unroll
        for (int jh = 0; jh < 2; jh++) {
            int col = n0 + cb + jh * 64;
            float4 o;
            float v0 = acc[i][jh * 4 + 0], v1 = acc[i][jh * 4 + 1];
            float v2 = acc[i][jh * 4 + 2], v3 = acc[i][jh * 4 + 3];
            if (MODE == 0) { v0 += bi; v1 += bi; v2 += bi; v3 += bi; }
            if (MODE == 2) {
                v0 = fmaf(v0, izp[col + 0], bwp[col + 0] * vb);
                v1 = fmaf(v1, izp[col + 1], bwp[col + 1] * vb);
                v2 = fmaf(v2, izp[col + 2], bwp[col + 2] * vb);
                v3 = fmaf(v3, izp[col + 3], bwp[col + 3] * vb);
            }
            o.x = v0; o.y = v1; o.z = v2; o.w = v3;
            *(float4*)&C[(size_t)row * N + col] = o;
        }
    }
}

// ---- per-channel BN stats -> affine a,d; also border key/value vectors ----
__global__ void stats_k(const float* __restrict__ bq, const float* __restrict__ gq, const float* __restrict__ betaq,
                        const float* __restrict__ bk, const float* __restrict__ gk, const float* __restrict__ betak,
                        const float* __restrict__ bv, const float* __restrict__ gv, const float* __restrict__ betav)
{
    int c = blockIdx.x;      // 0..255
    int t = blockIdx.y;      // 0:Q 1:K 2:V
    const float* src = (t == 0) ? g_qc : (t == 1) ? g_kc : g_vc;
    int tid = threadIdx.x;
    float s1 = 0.f, s2 = 0.f;
    for (int b = 0; b < NB; b++) {
        const float* p = src + ((size_t)b * NC + c) * NPIX;
        for (int i = tid; i < NPIX; i += 256) {
            float v = p[i];
            s1 += v; s2 += v * v;
        }
    }
    __shared__ double r1[256], r2[256];
    r1[tid] = s1; r2[tid] = s2;
    __syncthreads();
    for (int s = 128; s > 0; s >>= 1) {
        if (tid < s) { r1[tid] += r1[tid + s]; r2[tid] += r2[tid + s]; }
        __syncthreads();
    }
    if (tid == 0) {
        double S1 = r1[0], S2 = r2[0];
        double cnt = 16384.0;
        float bias = (t == 0) ? bq[c] : (t == 1) ? bk[c] : bv[c];
        float g    = (t == 0) ? gq[c] : (t == 1) ? gk[c] : gv[c];
        float be   = (t == 0) ? betaq[c] : (t == 1) ? betak[c] : betav[c];
        if (t > 0) {   // K,V include 260*4 border positions whose value == bias
            cnt = 17424.0;
            S1 += 1040.0 * (double)bias;
            S2 += 1040.0 * (double)bias * (double)bias;
        }
        double mean = S1 / cnt;
        double var  = S2 / cnt - mean * mean;
        float a = g * rsqrtf((float)var + 1e-5f);
        float d = be - a * (float)mean;
        g_a[t * NC + c] = a;
        g_dd[t * NC + c] = d;
        if (t == 1) g_kbv[c] = fmaf(a, bias, d);
        if (t == 2) g_vbv[c] = fmaf(a, bias, d);
    }
}

// ---- apply BN affine in place to Qc,Kc,Vc (float4) ----
__global__ void norm_k() {
    size_t idx = (size_t)blockIdx.x * 256 + threadIdx.x;  // float4 index, total 3*1048576
    int t = (int)(idx / 1048576);
    size_t rem = idx % 1048576;
    int c = (int)((rem >> 10) & 255);
    float a = g_a[t * NC + c], d = g_dd[t * NC + c];
    float4* p = (float4*)((t == 0) ? g_qc : (t == 1) ? g_kc : g_vc);
    float4 v = p[rem];
    v.x = fmaf(a, v.x, d); v.y = fmaf(a, v.y, d);
    v.z = fmaf(a, v.z, d); v.w = fmaf(a, v.w, d);
    p[rem] = v;
}

// ---- transpose Vn [c][k] -> Vt [k][c] per batch ----
__global__ void vtrans_k() {
    __shared__ float tile[32][33];
    int b = blockIdx.z;
    int k0 = blockIdx.x * 32, c0 = blockIdx.y * 32;
    int tx = threadIdx.x, ty = threadIdx.y;   // 32x8
    const float* src = g_vc + (size_t)b * NC * NPIX;
    float* dst = g_vt + (size_t)b * NC * NPIX;
    for (int j = 0; j < 32; j += 8)
        tile[ty + j][tx] = src[(size_t)(c0 + ty + j) * NPIX + k0 + tx];
    __syncthreads();
    for (int j = 0; j < 32; j += 8)
        dst[(size_t)(k0 + ty + j) * NC + c0 + tx] = tile[tx][ty + j];
}

// ---- border key score per query: sb[b][q] = dot(kbv, Qn[:,q]) ----
__global__ void sb_k() {
    int b = blockIdx.y;
    int q = blockIdx.x * 256 + threadIdx.x;
    const float* Q = g_qc + (size_t)b * NC * NPIX;
    float s = 0.f;
#pragma unroll 8
    for (int c = 0; c < NC; c++)
        s = fmaf(g_kbv[c], Q[(size_t)c * NPIX + q], s);
    g_sb[b * NPIX + q] = s;
}

// ---- softmax: partial max over 128-key chunks ----
__global__ void sm_max() {
    int b = blockIdx.z, kc = blockIdx.y;
    int q = blockIdx.x * 256 + threadIdx.x;
    const float* Sp = g_S + (size_t)b * NPIX * NPIX + (size_t)kc * 128 * NPIX + q;
    float m = -3.4e38f;
#pragma unroll 8
    for (int k = 0; k < 128; k++) m = fmaxf(m, Sp[(size_t)k * NPIX]);
    g_pred[((size_t)(b * NKC + kc)) * NPIX + q] = m;
}

// ---- combine maxes (+ border score) ----
__global__ void sm_maxc() {
    int b = blockIdx.y;
    int q = blockIdx.x * 256 + threadIdx.x;
    float m = g_sb[b * NPIX + q];
#pragma unroll
    for (int kc = 0; kc < NKC; kc++)
        m = fmaxf(m, g_pred[((size_t)(b * NKC + kc)) * NPIX + q]);
    g_m[b * NPIX + q] = m;
}

// ---- exp in place + partial sums ----
__global__ void sm_exp() {
    int b = blockIdx.z, kc = blockIdx.y;
    int q = blockIdx.x * 256 + threadIdx.x;
    float m = g_m[b * NPIX + q];
    float* Sp = g_S + (size_t)b * NPIX * NPIX + (size_t)kc * 128 * NPIX + q;
    float s = 0.f;
#pragma unroll 4
    for (int k = 0; k < 128; k++) {
        float e = fexp(Sp[(size_t)k * NPIX] - m);
        Sp[(size_t)k * NPIX] = e;
        s += e;
    }
    g_pred[((size_t)(b * NKC + kc)) * NPIX + q] = s;
}

// ---- finalize: Z, 1/Z, border weight ----
__global__ void sm_fin() {
    int b = blockIdx.y;
    int q = blockIdx.x * 256 + threadIdx.x;
    float s = 0.f;
#pragma unroll
    for (int kc = 0; kc < NKC; kc++)
        s += g_pred[((size_t)(b * NKC + kc)) * NPIX + q];
    float eb = 260.f * fexp(g_sb[b * NPIX + q] - g_m[b * NPIX + q]);
    float Z = s + eb;
    float iz = 1.f / Z;
    g_iz[b * NPIX + q] = iz;
    g_bw[b * NPIX + q] = eb * iz;
}

// ---------------------------------------------------------------------------
extern "C" void kernel_launch(void* const* d_in, const int* in_sizes, int n_in,
                              void* d_out, int out_size)
{
    const float* x     = (const float*)d_in[0];
    const float* Wq    = (const float*)d_in[1];
    const float* bq    = (const float*)d_in[2];
    const float* gq    = (const float*)d_in[3];
    const float* betaq = (const float*)d_in[4];
    const float* Wk    = (const float*)d_in[5];
    const float* bk    = (const float*)d_in[6];
    const float* gk    = (const float*)d_in[7];
    const float* betak = (const float*)d_in[8];
    const float* Wv    = (const float*)d_in[9];
    const float* bv    = (const float*)d_in[10];
    const float* gv    = (const float*)d_in[11];
    const float* betav = (const float*)d_in[12];
    float* out = (float*)d_out;

    float *p_col, *p_wqt, *p_wkt, *p_wvt, *p_qc, *p_kc, *p_vc, *p_vt, *p_S, *p_iz, *p_bw, *p_vbv;
    cudaGetSymbolAddress((void**)&p_col, g_col);
    cudaGetSymbolAddress((void**)&p_wqt, g_wqt);
    cudaGetSymbolAddress((void**)&p_wkt, g_wkt);
    cudaGetSymbolAddress((void**)&p_wvt, g_wvt);
    cudaGetSymbolAddress((void**)&p_qc,  g_qc);
    cudaGetSymbolAddress((void**)&p_kc,  g_kc);
    cudaGetSymbolAddress((void**)&p_vc,  g_vc);
    cudaGetSymbolAddress((void**)&p_vt,  g_vt);
    cudaGetSymbolAddress((void**)&p_S,   g_S);
    cudaGetSymbolAddress((void**)&p_iz,  g_iz);
    cudaGetSymbolAddress((void**)&p_bw,  g_bw);
    cudaGetSymbolAddress((void**)&p_vbv, g_vbv);

    const size_t sBC = (size_t)NC * NPIX;        // 1048576
    const size_t sS  = (size_t)NPIX * NPIX;      // 16777216

    // 1. pad + weight transposes + im2col
    pad_x<<<(NB * NC * 66 * 66 + 255) / 256, 256>>>(x);
    wtrans<<<(KR * NC + 255) / 256, 256>>>(Wq, p_wqt, NC, KR);
    wtrans<<<(NC * NC + 255) / 256, 256>>>(Wk, p_wkt, NC, NC);
    wtrans<<<(NC * NC + 255) / 256, 256>>>(Wv, p_wvt, NC, NC);
    im2col_k<<<(int)(((size_t)NB * KR * NPIX) / 256), 256>>>();

    // 2. convs as GEMMs (+bias)
    gemm_tn<0><<<dim3(32, 2, NB), 256>>>(p_wqt, p_col, p_qc, NC, NPIX, KR,
                                         0, (size_t)KR * NPIX, sBC, bq, 0, 0, 0);
    gemm_tn<0><<<dim3(32, 2, NB), 256>>>(p_wkt, x, p_kc, NC, NPIX, NC,
                                         0, sBC, sBC, bk, 0, 0, 0);
    gemm_tn<0><<<dim3(32, 2, NB), 256>>>(p_wvt, x, p_vc, NC, NPIX, NC,
                                         0, sBC, sBC, bv, 0, 0, 0);

    // 3. BN stats + normalize + V transpose + border key scores
    stats_k<<<dim3(256, 3), 256>>>(bq, gq, betaq, bk, gk, betak, bv, gv, betav);
    norm_k<<<(3 * 1048576) / 256, 256>>>();
    vtrans_k<<<dim3(128, 8, NB), dim3(32, 8)>>>();
    sb_k<<<dim3(16, NB), 256>>>();

    // 4. scores S = Kn^T Qn
    gemm_tn<1><<<dim3(32, 32, NB), 256>>>(p_kc, p_qc, p_S, NPIX, NPIX, NC,
                                          sBC, sBC, sS, 0, 0, 0, 0);

    // 5. softmax over keys (incl. border key x260)
    sm_max<<<dim3(16, NKC, NB), 256>>>();
    sm_maxc<<<dim3(16, NB), 256>>>();
    sm_exp<<<dim3(16, NKC, NB), 256>>>();
    sm_fin<<<dim3(16, NB), 256>>>();

    // 6. out = Vn @ P  (epilogue applies 1/Z and border value)
    gemm_tn<2><<<dim3(32, 2, NB), 256>>>(p_vt, p_S, out, NC, NPIX, NPIX,
                                         sBC, sS, sBC, 0, p_iz, p_bw, p_vbv);
}

// round 3
// speedup vs baseline: 1.0005x; 1.0005x over previous
#include <cuda_runtime.h>
#include <math.h>
#include <stdint.h>

// ---------------------------------------------------------------------------
// ChannelAttentionLayer: Q=BN(conv3x3(x)), K=BN(conv1x1(x,pad1)), V likewise,
// scores = K^T Q (over channels), softmax over keys, out = V @ attn.
// Border trick: all 260 padded key positions per image share ONE key/value
// vector (conv of zeros = bias), so attention = 4096 interior keys + one
// border key with multiplicity 260.
// ---------------------------------------------------------------------------

#define NB   4
#define NC   256
#define NPIX 4096          // 64*64
#define KR   2304          // 256*9
#define NKC  32            // k-chunks of 128 in softmax reduction

// ---- static device scratch (no allocations allowed) ----
__device__ float g_xpad[(size_t)NB*NC*66*66];
__device__ float g_col [(size_t)NB*KR*NPIX];
__device__ float g_wqt [KR*NC];
__device__ float g_wkt [NC*NC];
__device__ float g_wvt [NC*NC];
__device__ float g_qc  [(size_t)NB*NC*NPIX];
__device__ float g_kc  [(size_t)NB*NC*NPIX];
__device__ float g_vc  [(size_t)NB*NC*NPIX];
__device__ float g_vt  [(size_t)NB*NPIX*NC];
__device__ float g_S   [(size_t)NB*NPIX*NPIX];   // 268 MB scores / exp buffer
__device__ float g_pred[(size_t)NB*NKC*NPIX];    // partial max / partial sum
__device__ float g_sb  [NB*NPIX];
__device__ float g_m   [NB*NPIX];
__device__ float g_iz  [NB*NPIX];
__device__ float g_bw  [NB*NPIX];
__device__ float g_a   [3*NC];
__device__ float g_dd  [3*NC];
__device__ float g_kbv [NC];
__device__ float g_vbv [NC];

// ---- fast exp: FFMA-only (no MUFU), rel err ~2.4e-6, exact enough for 1e-3 gate
__device__ __forceinline__ float fexp(float x) {
    x = fmaxf(x, -87.0f);
    float t = fmaf(x, 1.4426950408889634f, 12582912.0f);
    float i = t - 12582912.0f;                 // nearest int to x*log2e
    float f = fmaf(x, 1.4426950408889634f, -i);
    float y = f * 0.6931471805599453f;         // |y| <= 0.3466
    float p = fmaf(y, 0.0083333338f, 0.041666668f);
    p = fmaf(y, p, 0.16666667f);
    p = fmaf(y, p, 0.5f);
    p = fmaf(y, p, 1.0f);
    p = fmaf(y, p, 1.0f);
    int e = (int)i;
    return p * __int_as_float((e + 127) << 23);
}

// ---- zero-pad x into 66x66 grid ----
__global__ void pad_x(const float* __restrict__ x) {
    int idx = blockIdx.x * 256 + threadIdx.x;
    if (idx >= NB * NC * 66 * 66) return;
    int xx = idx % 66, yy = (idx / 66) % 66, bc = idx / (66 * 66);
    float v = 0.f;
    if (yy >= 1 && yy <= 64 && xx >= 1 && xx <= 64)
        v = x[(size_t)bc * NPIX + (yy - 1) * 64 + (xx - 1)];
    g_xpad[idx] = v;
}

// ---- weight transpose: wt[r*M+m] = w[m*K+r] ----
__global__ void wtrans(const float* __restrict__ w, float* __restrict__ wt, int M, int K) {
    int idx = blockIdx.x * 256 + threadIdx.x;
    if (idx >= M * K) return;
    int m = idx % M, r = idx / M;
    wt[idx] = w[(size_t)m * K + r];
}

// ---- im2col: col[b][ci*9+t][y*64+x] = xpad[b][ci][y+dy][x+dx] ----
__global__ void im2col_k() {
    size_t idx = (size_t)blockIdx.x * 256 + threadIdx.x;   // total NB*KR*NPIX
    int n = (int)(idx & 4095);
    size_t t1 = idx >> 12;
    int r = (int)(t1 % KR);
    int b = (int)(t1 / KR);
    int ci = r / 9, tt = r % 9, dy = tt / 3, dx = tt % 3;
    int y = n >> 6, xx = n & 63;
    g_col[idx] = g_xpad[(((size_t)(b * NC + ci)) * 66 + y + dy) * 66 + xx + dx];
}

// ---------------------------------------------------------------------------
// TN GEMM: C[m][n] = sum_r A[r][m] * B[r][n]   (A,B row-major over r)
// MODE 0: +bias[m]   MODE 1: raw   MODE 2: *invZ[n] + bw[n]*vbv[m]
// 128x128 tile, BK=16, 256 threads, 8x8 micro-tile, float4 everywhere.
// ---------------------------------------------------------------------------
template <int MODE>
__global__ __launch_bounds__(256, 2) void gemm_tn(
    const float* __restrict__ A, const float* __restrict__ B, float* __restrict__ C,
    int M, int N, int K, size_t sA, size_t sB, size_t sC,
    const float* __restrict__ bias, const float* __restrict__ invZ,
    const float* __restrict__ bw, const float* __restrict__ vbv)
{
    int bz = blockIdx.z;
    A += sA * bz; B += sB * bz; C += sC * bz;
    __shared__ float As[16][128];
    __shared__ float Bs[16][128];
    int tid = threadIdx.x;
    int m0 = blockIdx.y * 128, n0 = blockIdx.x * 128;
    int lr = tid >> 5, lc = (tid & 31) << 2;
    const float* Ag = A + (size_t)lr * M + m0 + lc;
    const float* Bg = B + (size_t)lr * N + n0 + lc;
    int ra = (tid >> 4) * 4, cb = (tid & 15) * 4;

    float acc[8][8];
#pragma unroll
    for (int i = 0; i < 8; i++)
#pragma unroll
        for (int j = 0; j < 8; j++) acc[i][j] = 0.f;

    for (int k0 = 0; k0 < K; k0 += 16) {
        float4 a0 = *(const float4*)Ag;
        float4 a1 = *(const float4*)(Ag + (size_t)8 * M);
        float4 b0 = *(const float4*)Bg;
        float4 b1 = *(const float4*)(Bg + (size_t)8 * N);
        __syncthreads();
        *(float4*)&As[lr][lc] = a0;  *(float4*)&As[lr + 8][lc] = a1;
        *(float4*)&Bs[lr][lc] = b0;  *(float4*)&Bs[lr + 8][lc] = b1;
        __syncthreads();
#pragma unroll
        for (int kk = 0; kk < 16; kk++) {
            float av[8], bv[8];
            *(float4*)&av[0] = *(float4*)&As[kk][ra];
            *(float4*)&av[4] = *(float4*)&As[kk][ra + 64];
            *(float4*)&bv[0] = *(float4*)&Bs[kk][cb];
            *(float4*)&bv[4] = *(float4*)&Bs[kk][cb + 64];
#pragma unroll
            for (int i = 0; i < 8; i++)
#pragma unroll
                for (int j = 0; j < 8; j++)
                    acc[i][j] = fmaf(av[i], bv[j], acc[i][j]);
        }
        Ag += (size_t)16 * M;
        Bg += (size_t)16 * N;
    }

    const float* izp = (MODE == 2) ? invZ + (size_t)bz * N : (const float*)0;
    const float* bwp = (MODE == 2) ? bw   + (size_t)bz * N : (const float*)0;
#pragma unroll
    for (int i = 0; i < 8; i++) {
        int row = m0 + ra + (i & 3) + ((i >> 2) << 6);
        float bi = (MODE == 0) ? bias[row] : 0.f;
        float vb = (MODE == 2) ? vbv[row] : 0.f;
#pragma unroll
        for (int jh = 0; jh < 2; jh++) {
            int col = n0 + cb + jh * 64;
            float4 o;
            float v0 = acc[i][jh * 4 + 0], v1 = acc[i][jh * 4 + 1];
            float v2 = acc[i][jh * 4 + 2], v3 = acc[i][jh * 4 + 3];
            if (MODE == 0) { v0 += bi; v1 += bi; v2 += bi; v3 += bi; }
            if (MODE == 2) {
                v0 = fmaf(v0, izp[col + 0], bwp[col + 0] * vb);
                v1 = fmaf(v1, izp[col + 1], bwp[col + 1] * vb);
                v2 = fmaf(v2, izp[col + 2], bwp[col + 2] * vb);
                v3 = fmaf(v3, izp[col + 3], bwp[col + 3] * vb);
            }
            o.x = v0; o.y = v1; o.z = v2; o.w = v3;
            *(float4*)&C[(size_t)row * N + col] = o;
        }
    }
}

// ---- per-channel BN stats -> affine a,d; also border key/value vectors ----
__global__ void stats_k(const float* __restrict__ bq, const float* __restrict__ gq, const float* __restrict__ betaq,
                        const float* __restrict__ bk, const float* __restrict__ gk, const float* __restrict__ betak,
                        const float* __restrict__ bv, const float* __restrict__ gv, const float* __restrict__ betav)
{
    int c = blockIdx.x;      // 0..255
    int t = blockIdx.y;      // 0:Q 1:K 2:V
    const float* src = (t == 0) ? g_qc : (t == 1) ? g_kc : g_vc;
    int tid = threadIdx.x;
    float s1 = 0.f, s2 = 0.f;
    for (int b = 0; b < NB; b++) {
        const float* p = src + ((size_t)b * NC + c) * NPIX;
        for (int i = tid; i < NPIX; i += 256) {
            float v = p[i];
            s1 += v; s2 += v * v;
        }
    }
    __shared__ double r1[256], r2[256];
    r1[tid] = s1; r2[tid] = s2;
    __syncthreads();
    for (int s = 128; s > 0; s >>= 1) {
        if (tid < s) { r1[tid] += r1[tid + s]; r2[tid] += r2[tid + s]; }
        __syncthreads();
    }
    if (tid == 0) {
        double S1 = r1[0], S2 = r2[0];
        double cnt = 16384.0;
        float bias = (t == 0) ? bq[c] : (t == 1) ? bk[c] : bv[c];
        float g    = (t == 0) ? gq[c] : (t == 1) ? gk[c] : gv[c];
        float be   = (t == 0) ? betaq[c] : (t == 1) ? betak[c] : betav[c];
        if (t > 0) {   // K,V include 260*4 border positions whose value == bias
            cnt = 17424.0;
            S1 += 1040.0 * (double)bias;
            S2 += 1040.0 * (double)bias * (double)bias;
        }
        double mean = S1 / cnt;
        double var  = S2 / cnt - mean * mean;
        float a = g * rsqrtf((float)var + 1e-5f);
        float d = be - a * (float)mean;
        g_a[t * NC + c] = a;
        g_dd[t * NC + c] = d;
        if (t == 1) g_kbv[c] = fmaf(a, bias, d);
        if (t == 2) g_vbv[c] = fmaf(a, bias, d);
    }
}

// ---- apply BN affine in place to Qc,Kc,Vc (float4) ----
__global__ void norm_k() {
    size_t idx = (size_t)blockIdx.x * 256 + threadIdx.x;  // float4 index, total 3*1048576
    int t = (int)(idx / 1048576);
    size_t rem = idx % 1048576;
    int c = (int)((rem >> 10) & 255);
    float a = g_a[t * NC + c], d = g_dd[t * NC + c];
    float4* p = (float4*)((t == 0) ? g_qc : (t == 1) ? g_kc : g_vc);
    float4 v = p[rem];
    v.x = fmaf(a, v.x, d); v.y = fmaf(a, v.y, d);
    v.z = fmaf(a, v.z, d); v.w = fmaf(a, v.w, d);
    p[rem] = v;
}

// ---- transpose Vn [c][k] -> Vt [k][c] per batch ----
__global__ void vtrans_k() {
    __shared__ float tile[32][33];
    int b = blockIdx.z;
    int k0 = blockIdx.x * 32, c0 = blockIdx.y * 32;
    int tx = threadIdx.x, ty = threadIdx.y;   // 32x8
    const float* src = g_vc + (size_t)b * NC * NPIX;
    float* dst = g_vt + (size_t)b * NC * NPIX;
    for (int j = 0; j < 32; j += 8)
        tile[ty + j][tx] = src[(size_t)(c0 + ty + j) * NPIX + k0 + tx];
    __syncthreads();
    for (int j = 0; j < 32; j += 8)
        dst[(size_t)(k0 + ty + j) * NC + c0 + tx] = tile[tx][ty + j];
}

// ---- border key score per query: sb[b][q] = dot(kbv, Qn[:,q]) ----
__global__ void sb_k() {
    int b = blockIdx.y;
    int q = blockIdx.x * 256 + threadIdx.x;
    const float* Q = g_qc + (size_t)b * NC * NPIX;
    float s = 0.f;
#pragma unroll 8
    for (int c = 0; c < NC; c++)
        s = fmaf(g_kbv[c], Q[(size_t)c * NPIX + q], s);
    g_sb[b * NPIX + q] = s;
}

// ---- softmax: partial max over 128-key chunks ----
__global__ void sm_max() {
    int b = blockIdx.z, kc = blockIdx.y;
    int q = blockIdx.x * 256 + threadIdx.x;
    const float* Sp = g_S + (size_t)b * NPIX * NPIX + (size_t)kc * 128 * NPIX + q;
    float m = -3.4e38f;
#pragma unroll 8
    for (int k = 0; k < 128; k++) m = fmaxf(m, Sp[(size_t)k * NPIX]);
    g_pred[((size_t)(b * NKC + kc)) * NPIX + q] = m;
}

// ---- combine maxes (+ border score) ----
__global__ void sm_maxc() {
    int b = blockIdx.y;
    int q = blockIdx.x * 256 + threadIdx.x;
    float m = g_sb[b * NPIX + q];
#pragma unroll
    for (int kc = 0; kc < NKC; kc++)
        m = fmaxf(m, g_pred[((size_t)(b * NKC + kc)) * NPIX + q]);
    g_m[b * NPIX + q] = m;
}

// ---- exp in place + partial sums ----
__global__ void sm_exp() {
    int b = blockIdx.z, kc = blockIdx.y;
    int q = blockIdx.x * 256 + threadIdx.x;
    float m = g_m[b * NPIX + q];
    float* Sp = g_S + (size_t)b * NPIX * NPIX + (size_t)kc * 128 * NPIX + q;
    float s = 0.f;
#pragma unroll 4
    for (int k = 0; k < 128; k++) {
        float e = fexp(Sp[(size_t)k * NPIX] - m);
        Sp[(size_t)k * NPIX] = e;
        s += e;
    }
    g_pred[((size_t)(b * NKC + kc)) * NPIX + q] = s;
}

// ---- finalize: Z, 1/Z, border weight ----
__global__ void sm_fin() {
    int b = blockIdx.y;
    int q = blockIdx.x * 256 + threadIdx.x;
    float s = 0.f;
#pragma unroll
    for (int kc = 0; kc < NKC; kc++)
        s += g_pred[((size_t)(b * NKC + kc)) * NPIX + q];
    float eb = 260.f * fexp(g_sb[b * NPIX + q] - g_m[b * NPIX + q]);
    float Z = s + eb;
    float iz = 1.f / Z;
    g_iz[b * NPIX + q] = iz;
    g_bw[b * NPIX + q] = eb * iz;
}

// ---------------------------------------------------------------------------
extern "C" void kernel_launch(void* const* d_in, const int* in_sizes, int n_in,
                              void* d_out, int out_size)
{
    const float* x     = (const float*)d_in[0];
    const float* Wq    = (const float*)d_in[1];
    const float* bq    = (const float*)d_in[2];
    const float* gq    = (const float*)d_in[3];
    const float* betaq = (const float*)d_in[4];
    const float* Wk    = (const float*)d_in[5];
    const float* bk    = (const float*)d_in[6];
    const float* gk    = (const float*)d_in[7];
    const float* betak = (const float*)d_in[8];
    const float* Wv    = (const float*)d_in[9];
    const float* bv    = (const float*)d_in[10];
    const float* gv    = (const float*)d_in[11];
    const float* betav = (const float*)d_in[12];
    float* out = (float*)d_out;

    float *p_col, *p_wqt, *p_wkt, *p_wvt, *p_qc, *p_kc, *p_vc, *p_vt, *p_S, *p_iz, *p_bw, *p_vbv;
    cudaGetSymbolAddress((void**)&p_col, g_col);
    cudaGetSymbolAddress((void**)&p_wqt, g_wqt);
    cudaGetSymbolAddress((void**)&p_wkt, g_wkt);
    cudaGetSymbolAddress((void**)&p_wvt, g_wvt);
    cudaGetSymbolAddress((void**)&p_qc,  g_qc);
    cudaGetSymbolAddress((void**)&p_kc,  g_kc);
    cudaGetSymbolAddress((void**)&p_vc,  g_vc);
    cudaGetSymbolAddress((void**)&p_vt,  g_vt);
    cudaGetSymbolAddress((void**)&p_S,   g_S);
    cudaGetSymbolAddress((void**)&p_iz,  g_iz);
    cudaGetSymbolAddress((void**)&p_bw,  g_bw);
    cudaGetSymbolAddress((void**)&p_vbv, g_vbv);

    const size_t sBC = (size_t)NC * NPIX;        // 1048576
    const size_t sS  = (size_t)NPIX * NPIX;      // 16777216

    // 1. pad + weight transposes + im2col
    pad_x<<<(NB * NC * 66 * 66 + 255) / 256, 256>>>(x);
    wtrans<<<(KR * NC + 255) / 256, 256>>>(Wq, p_wqt, NC, KR);
    wtrans<<<(NC * NC + 255) / 256, 256>>>(Wk, p_wkt, NC, NC);
    wtrans<<<(NC * NC + 255) / 256, 256>>>(Wv, p_wvt, NC, NC);
    im2col_k<<<(int)(((size_t)NB * KR * NPIX) / 256), 256>>>();

    // 2. convs as GEMMs (+bias)
    gemm_tn<0><<<dim3(32, 2, NB), 256>>>(p_wqt, p_col, p_qc, NC, NPIX, KR,
                                         0, (size_t)KR * NPIX, sBC, bq, 0, 0, 0);
    gemm_tn<0><<<dim3(32, 2, NB), 256>>>(p_wkt, x, p_kc, NC, NPIX, NC,
                                         0, sBC, sBC, bk, 0, 0, 0);
    gemm_tn<0><<<dim3(32, 2, NB), 256>>>(p_wvt, x, p_vc, NC, NPIX, NC,
                                         0, sBC, sBC, bv, 0, 0, 0);

    // 3. BN stats + normalize + V transpose + border key scores
    stats_k<<<dim3(256, 3), 256>>>(bq, gq, betaq, bk, gk, betak, bv, gv, betav);
    norm_k<<<(3 * 1048576) / 256, 256>>>();
    vtrans_k<<<dim3(128, 8, NB), dim3(32, 8)>>>();
    sb_k<<<dim3(16, NB), 256>>>();

    // 4. scores S = Kn^T Qn
    gemm_tn<1><<<dim3(32, 32, NB), 256>>>(p_kc, p_qc, p_S, NPIX, NPIX, NC,
                                          sBC, sBC, sS, 0, 0, 0, 0);

    // 5. softmax over keys (incl. border key x260)
    sm_max<<<dim3(16, NKC, NB), 256>>>();
    sm_maxc<<<dim3(16, NB), 256>>>();
    sm_exp<<<dim3(16, NKC, NB), 256>>>();
    sm_fin<<<dim3(16, NB), 256>>>();

    // 6. out = Vn @ P  (epilogue applies 1/Z and border value)
    gemm_tn<2><<<dim3(32, 2, NB), 256>>>(p_vt, p_S, out, NC, NPIX, NPIX,
                                         sBC, sS, sBC, 0, p_iz, p_bw, p_vbv);
}

// round 5
// speedup vs baseline: 1.5473x; 1.5466x over previous
#include <cuda_runtime.h>
#include <cuda_bf16.h>
#include <math.h>
#include <stdint.h>

#define NB 4
#define NC 256
#define NPIX 4096
#define KRR 2304

// ---- static device scratch ----
__device__ float g_xpad[(size_t)NB*NC*66*66];
__device__ __nv_bfloat16 g_wqh[(size_t)NC*3*KRR];
__device__ __nv_bfloat16 g_wkh[NC*768];
__device__ __nv_bfloat16 g_wvh[NC*768];
__device__ __nv_bfloat16 g_colh[(size_t)NB*NPIX*3*KRR];   // im2col, B-pattern [h,l,h]
__device__ __nv_bfloat16 g_xth[(size_t)NB*NPIX*768];      // x^T,   B-pattern
__device__ float g_qc[(size_t)NB*NC*NPIX];
__device__ float g_kc[(size_t)NB*NC*NPIX];
__device__ float g_vc[(size_t)NB*NC*NPIX];
__device__ __nv_bfloat16 g_qth[(size_t)NB*NPIX*768];      // BN(Q)^T, A-pattern [h,h,l]
__device__ __nv_bfloat16 g_kth[(size_t)NB*NPIX*768];      // BN(K)^T, B-pattern
__device__ __nv_bfloat16 g_vh[(size_t)NB*NC*12288];       // BN(V),   A-pattern
__device__ float g_S[(size_t)NB*NPIX*NPIX];               // scores [b][q][k]
__device__ __nv_bfloat16 g_ph[(size_t)NB*NPIX*12288];     // P*invZ,  B-pattern
__device__ float g_sb[NB*NPIX];
__device__ float g_bw[NB*NPIX];
__device__ float g_a[3*NC];
__device__ float g_dd[3*NC];
__device__ float g_kbv[NC];
__device__ float g_vbv[NC];

// ---- helpers ----
__device__ __forceinline__ uint32_t smem_u32(const void* p) {
    uint32_t a;
    asm("{ .reg .u64 t; cvta.to.shared.u64 t, %1; cvt.u32.u64 %0, t; }" : "=r"(a) : "l"(p));
    return a;
}
__device__ __forceinline__ void cpa16(uint32_t s, const void* g) {
    asm volatile("cp.async.cg.shared.global [%0], [%1], 16;" :: "r"(s), "l"(g));
}
__device__ __forceinline__ void ldm4(uint32_t* r, uint32_t addr) {
    asm volatile("ldmatrix.sync.aligned.m8n8.x4.shared.b16 {%0,%1,%2,%3}, [%4];"
                 : "=r"(r[0]), "=r"(r[1]), "=r"(r[2]), "=r"(r[3]) : "r"(addr));
}
__device__ __forceinline__ void mma16(float* d, const uint32_t* a, uint32_t b0, uint32_t b1) {
    asm volatile(
        "mma.sync.aligned.m16n8k16.row.col.f32.bf16.bf16.f32 "
        "{%0,%1,%2,%3}, {%4,%5,%6,%7}, {%8,%9}, {%0,%1,%2,%3};"
        : "+f"(d[0]), "+f"(d[1]), "+f"(d[2]), "+f"(d[3])
        : "r"(a[0]), "r"(a[1]), "r"(a[2]), "r"(a[3]), "r"(b0), "r"(b1));
}

__device__ __forceinline__ float fexp(float x) {
    x = fmaxf(x, -87.0f);
    float t = fmaf(x, 1.4426950408889634f, 12582912.0f);
    float i = t - 12582912.0f;
    float f = fmaf(x, 1.4426950408889634f, -i);
    float y = f * 0.6931471805599453f;
    float p = fmaf(y, 0.0083333338f, 0.041666668f);
    p = fmaf(y, p, 0.16666667f);
    p = fmaf(y, p, 0.5f);
    p = fmaf(y, p, 1.0f);
    p = fmaf(y, p, 1.0f);
    return p * __int_as_float(((int)i + 127) << 23);
}
__device__ __forceinline__ void split2(float v, __nv_bfloat16& h, __nv_bfloat16& l) {
    h = __float2bfloat16(v);
    l = __float2bfloat16(v - __bfloat162float(h));
}

// ---------------------------------------------------------------------------
// HMMA bf16 GEMM: C[m][n] = sum_k A[m][k]*B[n][k], row stride of C = 4096.
// BM=BN=128, BK=32. 8 warps (2x4), warp tile 64x32, m16n8k16 mma.sync.
// Smem rows padded to 80B -> conflict-free cp.async stores + ldmatrix reads.
// MODE 0:+bias[m]  1:raw  2:+bw[bz][n]*vbv[m]
// ---------------------------------------------------------------------------
#define STR 80
#define STAGE (128*STR)
#define GSMEM (6*STAGE)    // 3 stages x (A+B) = 61440

template <int MODE>
__global__ __launch_bounds__(256, 1) void gemm_bf(
    const __nv_bfloat16* __restrict__ A, const __nv_bfloat16* __restrict__ B,
    float* __restrict__ C, int Kp, size_t sA, size_t sB, size_t sC,
    const float* __restrict__ bias, const float* __restrict__ bw, const float* __restrict__ vbv)
{
    extern __shared__ char sm_[];
    uint32_t smb = smem_u32(sm_);
    int tid = threadIdx.x, lane = tid & 31, wid = tid >> 5;
    int wm = wid & 1, wn = wid >> 1;
    int bz = blockIdx.z;
    int m0 = blockIdx.y * 128, n0 = blockIdx.x * 128;
    const __nv_bfloat16* Ab = A + sA * bz + (size_t)m0 * Kp;
    const __nv_bfloat16* Bb = B + sB * bz + (size_t)n0 * Kp;
    const int nk = Kp >> 5;

    auto load = [&](int kt) {
        int st = kt % 3;
        uint32_t as = smb + st * STAGE;
        uint32_t bs = smb + 3 * STAGE + st * STAGE;
        int k0 = kt * 32;
#pragma unroll
        for (int i = 0; i < 2; i++) {
            int e = tid + i * 256;
            int row = e >> 2, ch = e & 3;
            cpa16(as + row * STR + ch * 16, Ab + (size_t)row * Kp + k0 + ch * 8);
            cpa16(bs + row * STR + ch * 16, Bb + (size_t)row * Kp + k0 + ch * 8);
        }
        asm volatile("cp.async.commit_group;" ::: "memory");
    };

    float acc[4][4][4];
#pragma unroll
    for (int i = 0; i < 4; i++)
#pragma unroll
        for (int j = 0; j < 4; j++)
#pragma unroll
            for (int r = 0; r < 4; r++) acc[i][j][r] = 0.f;

    load(0);
    load(1);
    for (int kt = 0; kt < nk; kt++) {
        asm volatile("cp.async.wait_group 1;" ::: "memory");
        __syncthreads();
        int st = kt % 3;
        uint32_t as = smb + st * STAGE + (wm * 64 + (lane & 15)) * STR + (lane >> 4) * 16;
        uint32_t bs = smb + 3 * STAGE + st * STAGE + (wn * 32 + (lane & 15)) * STR + (lane >> 4) * 16;
#pragma unroll
        for (int kk = 0; kk < 2; kk++) {
            uint32_t a[4][4], b[2][4];
#pragma unroll
            for (int mt = 0; mt < 4; mt++) ldm4(a[mt], as + mt * 16 * STR + kk * 32);
#pragma unroll
            for (int nt = 0; nt < 2; nt++) ldm4(b[nt], bs + nt * 16 * STR + kk * 32);
#pragma unroll
            for (int mt = 0; mt < 4; mt++)
#pragma unroll
                for (int n8 = 0; n8 < 4; n8++)
                    mma16(acc[mt][n8], a[mt], b[n8 >> 1][n8 & 1], b[n8 >> 1][(n8 & 1) + 2]);
        }
        __syncthreads();
        if (kt + 2 < nk) load(kt + 2);
        else asm volatile("cp.async.commit_group;" ::: "memory");
    }

    // epilogue
    float* Cb = C + sC * bz;
    const float* bwp = (MODE == 2) ? bw + (size_t)bz * 4096 : (const float*)0;
#pragma unroll
    for (int mt = 0; mt < 4; mt++) {
        int row = m0 + wm * 64 + mt * 16 + (lane >> 2);
        float bi0 = 0.f, bi1 = 0.f, vb0 = 0.f, vb1 = 0.f;
        if (MODE == 0) { bi0 = bias[row]; bi1 = bias[row + 8]; }
        if (MODE == 2) { vb0 = vbv[row]; vb1 = vbv[row + 8]; }
#pragma unroll
        for (int n8 = 0; n8 < 4; n8++) {
            int col = n0 + wn * 32 + n8 * 8 + (lane & 3) * 2;
            float2 v0, v1;
            v0.x = acc[mt][n8][0]; v0.y = acc[mt][n8][1];
            v1.x = acc[mt][n8][2]; v1.y = acc[mt][n8][3];
            if (MODE == 0) { v0.x += bi0; v0.y += bi0; v1.x += bi1; v1.y += bi1; }
            if (MODE == 2) {
                float w0 = bwp[col], w1 = bwp[col + 1];
                v0.x = fmaf(w0, vb0, v0.x); v0.y = fmaf(w1, vb0, v0.y);
                v1.x = fmaf(w0, vb1, v1.x); v1.y = fmaf(w1, vb1, v1.y);
            }
            *(float2*)&Cb[(size_t)row * 4096 + col] = v0;
            *(float2*)&Cb[(size_t)(row + 8) * 4096 + col] = v1;
        }
    }
}

// ---- prep kernels ----
__global__ void pad_x(const float* __restrict__ x) {
    int idx = blockIdx.x * 256 + threadIdx.x;
    if (idx >= NB * NC * 66 * 66) return;
    int xx = idx % 66, yy = (idx / 66) % 66, bc = idx / (66 * 66);
    float v = 0.f;
    if (yy >= 1 && yy <= 64 && xx >= 1 && xx <= 64)
        v = x[(size_t)bc * NPIX + (yy - 1) * 64 + (xx - 1)];
    g_xpad[idx] = v;
}

// weights: A-pattern [hi,hi,lo]
__global__ void wsplit(const float* __restrict__ w, __nv_bfloat16* __restrict__ o, int KB) {
    int idx = blockIdx.x * 256 + threadIdx.x;
    if (idx >= NC * KB) return;
    int m = idx / KB, r = idx % KB;
    __nv_bfloat16 h, l;
    split2(w[idx], h, l);
    size_t base = (size_t)m * 3 * KB + r;
    o[base] = h; o[base + KB] = h; o[base + 2 * KB] = l;
}

// im2col + split: B-pattern [hi,lo,hi], 8 r's per thread
__global__ void im2col_s() {
    int idx = blockIdx.x * 256 + threadIdx.x;     // 4*4096*288
    int r8 = idx % 288;
    int t1 = idx / 288;
    int pix = t1 & 4095, b = t1 >> 12;
    int y = pix >> 6, xx = pix & 63;
    __nv_bfloat16 h[8], l[8];
    int r0 = r8 * 8;
#pragma unroll
    for (int j = 0; j < 8; j++) {
        int r = r0 + j, c = r / 9, t = r % 9, dy = t / 3, dx = t % 3;
        float v = g_xpad[(((size_t)(b * NC + c)) * 66 + y + dy) * 66 + xx + dx];
        split2(v, h[j], l[j]);
    }
    __nv_bfloat16* o = g_colh + ((size_t)(b * 4096 + pix)) * 6912 + r0;
    *(uint4*)o = *(uint4*)h;
    *(uint4*)(o + 2304) = *(uint4*)l;
    *(uint4*)(o + 4608) = *(uint4*)h;
}

// transpose [c][pix] -> [pix][c3] with optional affine; patA: [hi,hi,lo] else [hi,lo,hi]
__global__ void tsplit(const float* __restrict__ src, __nv_bfloat16* __restrict__ dst,
                       const float* __restrict__ aa, const float* __restrict__ ad, int patA) {
    __shared__ float tile[32][33];
    int b = blockIdx.z;
    int p0 = blockIdx.x * 32, c0 = blockIdx.y * 32;
    int tx = threadIdx.x, ty = threadIdx.y;    // 32x8
    const float* s = src + (size_t)b * NC * NPIX;
    for (int j = 0; j < 32; j += 8) {
        float a = aa ? aa[c0 + ty + j] : 1.f;
        float d = ad ? ad[c0 + ty + j] : 0.f;
        tile[ty + j][tx] = fmaf(a, s[(size_t)(c0 + ty + j) * NPIX + p0 + tx], d);
    }
    __syncthreads();
    for (int j = 0; j < 32; j += 8) {
        __nv_bfloat16 h, l;
        split2(tile[tx][ty + j], h, l);
        __nv_bfloat16* o = dst + ((size_t)b * 4096 + p0 + ty + j) * 768 + c0 + tx;
        o[0] = h;
        o[256] = patA ? h : l;
        o[512] = patA ? l : h;
    }
}

// V: elementwise affine+split, A-pattern over k-blocks of 4096
__global__ void vsplit() {
    size_t i4 = (size_t)blockIdx.x * 256 + threadIdx.x;   // NB*NC*NPIX/4
    size_t e = i4 * 4;
    int c = (int)((e >> 12) & 255);
    int b = (int)(e >> 20);
    int k = (int)(e & 4095);
    float a = g_a[512 + c], d = g_dd[512 + c];
    float4 v = *(float4*)(g_vc + e);
    __nv_bfloat16 h[4], l[4];
    split2(fmaf(a, v.x, d), h[0], l[0]);
    split2(fmaf(a, v.y, d), h[1], l[1]);
    split2(fmaf(a, v.z, d), h[2], l[2]);
    split2(fmaf(a, v.w, d), h[3], l[3]);
    __nv_bfloat16* o = g_vh + ((size_t)(b * 256 + c)) * 12288 + k;
    *(uint2*)o = *(uint2*)h;
    *(uint2*)(o + 4096) = *(uint2*)h;
    *(uint2*)(o + 8192) = *(uint2*)l;
}

// BN stats (raw conv outputs) -> affine + border vectors
__global__ void stats_k(const float* __restrict__ bq, const float* __restrict__ gq, const float* __restrict__ betaq,
                        const float* __restrict__ bk, const float* __restrict__ gk, const float* __restrict__ betak,
                        const float* __restrict__ bv, const float* __restrict__ gv, const float* __restrict__ betav)
{
    int c = blockIdx.x, t = blockIdx.y;
    const float* src = (t == 0) ? g_qc : (t == 1) ? g_kc : g_vc;
    int tid = threadIdx.x;
    float s1 = 0.f, s2 = 0.f;
    for (int b = 0; b < NB; b++) {
        const float* p = src + ((size_t)b * NC + c) * NPIX;
        for (int i = tid; i < NPIX; i += 256) {
            float v = p[i];
            s1 += v; s2 += v * v;
        }
    }
    __shared__ double r1[256], r2[256];
    r1[tid] = s1; r2[tid] = s2;
    __syncthreads();
    for (int s = 128; s > 0; s >>= 1) {
        if (tid < s) { r1[tid] += r1[tid + s]; r2[tid] += r2[tid + s]; }
        __syncthreads();
    }
    if (tid == 0) {
        double S1 = r1[0], S2 = r2[0], cnt = 16384.0;
        float bias = (t == 0) ? bq[c] : (t == 1) ? bk[c] : bv[c];
        float g    = (t == 0) ? gq[c] : (t == 1) ? gk[c] : gv[c];
        float be   = (t == 0) ? betaq[c] : (t == 1) ? betak[c] : betav[c];
        if (t > 0) {
            cnt = 17424.0;
            S1 += 1040.0 * (double)bias;
            S2 += 1040.0 * (double)bias * (double)bias;
        }
        double mean = S1 / cnt;
        double var = S2 / cnt - mean * mean;
        float a = g * rsqrtf((float)var + 1e-5f);
        float d = be - a * (float)mean;
        g_a[t * NC + c] = a;
        g_dd[t * NC + c] = d;
        if (t == 1) g_kbv[c] = fmaf(a, bias, d);
        if (t == 2) g_vbv[c] = fmaf(a, bias, d);
    }
}

// border key score per query (applies Q affine inline)
__global__ void sb_k() {
    int b = blockIdx.y;
    int q = blockIdx.x * 256 + threadIdx.x;
    const float* Q = g_qc + (size_t)b * NC * NPIX;
    float s = 0.f;
#pragma unroll 8
    for (int c = 0; c < NC; c++) {
        float qn = fmaf(g_a[c], Q[(size_t)c * NPIX + q], g_dd[c]);
        s = fmaf(g_kbv[c], qn, s);
    }
    g_sb[b * NPIX + q] = s;
}

// row softmax over keys (incl. border x260), write phat = p*invZ (B-pattern) + bw
__global__ __launch_bounds__(256) void softmax_k() {
    int row = blockIdx.x;          // b*4096 + q
    int t = threadIdx.x;
    const float4* Sp = (const float4*)(g_S + (size_t)row * 4096);
    float4 v[4];
    float m = -3.4e38f;
#pragma unroll
    for (int j = 0; j < 4; j++) {
        v[j] = Sp[t * 4 + j];
        m = fmaxf(m, fmaxf(fmaxf(v[j].x, v[j].y), fmaxf(v[j].z, v[j].w)));
    }
    __shared__ float red[256];
    red[t] = m;
    __syncthreads();
    for (int s = 128; s > 0; s >>= 1) {
        if (t < s) red[t] = fmaxf(red[t], red[t + s]);
        __syncthreads();
    }
    float sbv = g_sb[row];
    m = fmaxf(red[0], sbv);
    __syncthreads();
    float e16[16], s = 0.f;
#pragma unroll
    for (int j = 0; j < 4; j++) {
        e16[j*4+0] = fexp(v[j].x - m); e16[j*4+1] = fexp(v[j].y - m);
        e16[j*4+2] = fexp(v[j].z - m); e16[j*4+3] = fexp(v[j].w - m);
        s += e16[j*4+0] + e16[j*4+1] + e16[j*4+2] + e16[j*4+3];
    }
    red[t] = s;
    __syncthreads();
    for (int st = 128; st > 0; st >>= 1) {
        if (t < st) red[t] += red[t + st];
        __syncthreads();
    }
    float eb = 260.f * fexp(sbv - m);
    float iz = 1.f / (red[0] + eb);
    if (t == 0) g_bw[row] = eb * iz;
    __nv_bfloat16 h[16], l[16];
#pragma unroll
    for (int j = 0; j < 16; j++) split2(e16[j] * iz, h[j], l[j]);
    __nv_bfloat16* o = g_ph + (size_t)row * 12288 + t * 16;
    *(uint4*)o = *(uint4*)h;            *(uint4*)(o + 8) = *(uint4*)(h + 8);
    *(uint4*)(o + 4096) = *(uint4*)l;   *(uint4*)(o + 4104) = *(uint4*)(l + 8);
    *(uint4*)(o + 8192) = *(uint4*)h;   *(uint4*)(o + 8200) = *(uint4*)(h + 8);
}

// ---------------------------------------------------------------------------
extern "C" void kernel_launch(void* const* d_in, const int* in_sizes, int n_in,
                              void* d_out, int out_size)
{
    const float* x     = (const float*)d_in[0];
    const float* Wq    = (const float*)d_in[1];
    const float* bq    = (const float*)d_in[2];
    const float* gq    = (const float*)d_in[3];
    const float* betaq = (const float*)d_in[4];
    const float* Wk    = (const float*)d_in[5];
    const float* bk    = (const float*)d_in[6];
    const float* gk    = (const float*)d_in[7];
    const float* betak = (const float*)d_in[8];
    const float* Wv    = (const float*)d_in[9];
    const float* bv    = (const float*)d_in[10];
    const float* gv    = (const float*)d_in[11];
    const float* betav = (const float*)d_in[12];
    float* out = (float*)d_out;

    cudaFuncSetAttribute(gemm_bf<0>, cudaFuncAttributeMaxDynamicSharedMemorySize, GSMEM);
    cudaFuncSetAttribute(gemm_bf<1>, cudaFuncAttributeMaxDynamicSharedMemorySize, GSMEM);
    cudaFuncSetAttribute(gemm_bf<2>, cudaFuncAttributeMaxDynamicSharedMemorySize, GSMEM);

    __nv_bfloat16 *p_wqh, *p_wkh, *p_wvh, *p_colh, *p_xth, *p_qth, *p_kth, *p_vh, *p_ph;
    float *p_qc, *p_kc, *p_vc, *p_S, *p_a, *p_dd, *p_bw, *p_vbv;
    cudaGetSymbolAddress((void**)&p_wqh, g_wqh);
    cudaGetSymbolAddress((void**)&p_wkh, g_wkh);
    cudaGetSymbolAddress((void**)&p_wvh, g_wvh);
    cudaGetSymbolAddress((void**)&p_colh, g_colh);
    cudaGetSymbolAddress((void**)&p_xth, g_xth);
    cudaGetSymbolAddress((void**)&p_qth, g_qth);
    cudaGetSymbolAddress((void**)&p_kth, g_kth);
    cudaGetSymbolAddress((void**)&p_vh,  g_vh);
    cudaGetSymbolAddress((void**)&p_ph,  g_ph);
    cudaGetSymbolAddress((void**)&p_qc,  g_qc);
    cudaGetSymbolAddress((void**)&p_kc,  g_kc);
    cudaGetSymbolAddress((void**)&p_vc,  g_vc);
    cudaGetSymbolAddress((void**)&p_S,   g_S);
    cudaGetSymbolAddress((void**)&p_a,   g_a);
    cudaGetSymbolAddress((void**)&p_dd,  g_dd);
    cudaGetSymbolAddress((void**)&p_bw,  g_bw);
    cudaGetSymbolAddress((void**)&p_vbv, g_vbv);

    const size_t sBC = (size_t)NC * NPIX;
    const size_t sS  = (size_t)NPIX * NPIX;

    // 1. prep: pad, weight splits, im2col split, x^T split
    pad_x<<<(NB * NC * 66 * 66 + 255) / 256, 256>>>(x);
    wsplit<<<(NC * KRR + 255) / 256, 256>>>(Wq, p_wqh, KRR);
    wsplit<<<(NC * NC + 255) / 256, 256>>>(Wk, p_wkh, NC);
    wsplit<<<(NC * NC + 255) / 256, 256>>>(Wv, p_wvh, NC);
    im2col_s<<<(NB * 4096 * 288) / 256, 256>>>();
    tsplit<<<dim3(128, 8, NB), dim3(32, 8)>>>(x, p_xth, 0, 0, 0);

    // 2. convs on HMMA (raw fp32 out + bias)
    gemm_bf<0><<<dim3(32, 2, NB), 256, GSMEM>>>(p_wqh, p_colh, p_qc, 6912,
        0, (size_t)4096 * 6912, sBC, bq, 0, 0);
    gemm_bf<0><<<dim3(32, 2, NB), 256, GSMEM>>>(p_wkh, p_xth, p_kc, 768,
        0, (size_t)4096 * 768, sBC, bk, 0, 0);
    gemm_bf<0><<<dim3(32, 2, NB), 256, GSMEM>>>(p_wvh, p_xth, p_vc, 768,
        0, (size_t)4096 * 768, sBC, bv, 0, 0);

    // 3. BN stats + splits (affine fused) + border scores
    stats_k<<<dim3(256, 3), 256>>>(bq, gq, betaq, bk, gk, betak, bv, gv, betav);
    tsplit<<<dim3(128, 8, NB), dim3(32, 8)>>>(p_qc, p_qth, p_a, p_dd, 1);
    tsplit<<<dim3(128, 8, NB), dim3(32, 8)>>>(p_kc, p_kth, p_a + 256, p_dd + 256, 0);
    vsplit<<<(int)(((size_t)NB * NC * NPIX / 4) / 256), 256>>>();
    sb_k<<<dim3(16, NB), 256>>>();

    // 4. S[q][k] = Qn^T Kn
    gemm_bf<1><<<dim3(32, 32, NB), 256, GSMEM>>>(p_qth, p_kth, p_S, 768,
        (size_t)4096 * 768, (size_t)4096 * 768, sS, 0, 0, 0);

    // 5. softmax rows -> phat (p*invZ, split) + border weights
    softmax_k<<<NB * NPIX, 256>>>();

    // 6. out = Vn @ P  (epilogue adds bw[q]*vbv[c])
    gemm_bf<2><<<dim3(32, 2, NB), 256, GSMEM>>>(p_vh, p_ph, out, 12288,
        (size_t)NC * 12288, (size_t)4096 * 12288, sBC, 0, p_bw, p_vbv);
}

// round 6
// speedup vs baseline: 1.7734x; 1.1461x over previous
#include <cuda_runtime.h>
#include <cuda_bf16.h>
#include <math.h>
#include <stdint.h>

#define NB 4
#define NC 256
#define NPIX 4096
#define STR 80

// ---- static device scratch ----
__device__ __nv_bfloat16 g_xt_h[(size_t)NB*4356*256];   // padded x, [b][pix66][c] hi
__device__ __nv_bfloat16 g_xt_l[(size_t)NB*4356*256];   // lo
__device__ __nv_bfloat16 g_wqh[NC*6912];                // Wq split, A-pat [h,h,l], k=t*256+c
__device__ __nv_bfloat16 g_wkh[NC*768];
__device__ __nv_bfloat16 g_wvh[NC*768];
__device__ float g_qc[(size_t)NB*NC*NPIX];
__device__ float g_kc[(size_t)NB*NC*NPIX];
__device__ float g_vc[(size_t)NB*NC*NPIX];
__device__ __nv_bfloat16 g_qth[(size_t)NB*NPIX*768];    // BN(Q)^T, A-pat
__device__ __nv_bfloat16 g_kth[(size_t)NB*NPIX*768];    // BN(K)^T, B-pat
__device__ __nv_bfloat16 g_vh2[(size_t)NB*2*NC*NPIX];   // BN(V) hi | lo, [b][hl][c][k]
__device__ float g_S[(size_t)NB*NPIX*NPIX];             // scores [b][q][k]
__device__ float g_sb[NB*NPIX];
__device__ float g_bw[NB*NPIX];
__device__ float g_m[NB*NPIX];
__device__ float g_iz[NB*NPIX];
__device__ float g_a[3*NC];
__device__ float g_dd[3*NC];
__device__ float g_kbv[NC];
__device__ float g_vbv[NC];

// ---- helpers ----
__device__ __forceinline__ uint32_t smem_u32(const void* p) {
    uint32_t a;
    asm("{ .reg .u64 t; cvta.to.shared.u64 t, %1; cvt.u32.u64 %0, t; }" : "=r"(a) : "l"(p));
    return a;
}
__device__ __forceinline__ void cpa16(uint32_t s, const void* g) {
    asm volatile("cp.async.cg.shared.global [%0], [%1], 16;" :: "r"(s), "l"(g));
}
__device__ __forceinline__ void ldm4(uint32_t* r, uint32_t addr) {
    asm volatile("ldmatrix.sync.aligned.m8n8.x4.shared.b16 {%0,%1,%2,%3}, [%4];"
                 : "=r"(r[0]), "=r"(r[1]), "=r"(r[2]), "=r"(r[3]) : "r"(addr));
}
__device__ __forceinline__ void mma16(float* d, const uint32_t* a, uint32_t b0, uint32_t b1) {
    asm volatile(
        "mma.sync.aligned.m16n8k16.row.col.f32.bf16.bf16.f32 "
        "{%0,%1,%2,%3}, {%4,%5,%6,%7}, {%8,%9}, {%0,%1,%2,%3};"
        : "+f"(d[0]), "+f"(d[1]), "+f"(d[2]), "+f"(d[3])
        : "r"(a[0]), "r"(a[1]), "r"(a[2]), "r"(a[3]), "r"(b0), "r"(b1));
}
__device__ __forceinline__ float fexp(float x) {
    x = fmaxf(x, -87.0f);
    float t = fmaf(x, 1.4426950408889634f, 12582912.0f);
    float i = t - 12582912.0f;
    float f = fmaf(x, 1.4426950408889634f, -i);
    float y = f * 0.6931471805599453f;
    float p = fmaf(y, 0.0083333338f, 0.041666668f);
    p = fmaf(y, p, 0.16666667f);
    p = fmaf(y, p, 0.5f);
    p = fmaf(y, p, 1.0f);
    p = fmaf(y, p, 1.0f);
    return p * __int_as_float(((int)i + 127) << 23);
}
__device__ __forceinline__ void split2(float v, __nv_bfloat16& h, __nv_bfloat16& l) {
    h = __float2bfloat16(v);
    l = __float2bfloat16(v - __bfloat162float(h));
}

// ---------------------------------------------------------------------------
// Implicit-im2col conv GEMM: C[m=oc][n=pix] = sum_k' W[m][k'] * xt[pix,k']
// BM=256(all oc), BN=128, BK=32. 8 warps 4x2, warp tile 64x64.
// k' = blk*(TAPS*256) + t*256 + c; B buffer: blk==1 -> lo else hi (B-pat h,l,h).
// ---------------------------------------------------------------------------
#define CSTAGE (256*STR + 128*STR)   // 30720
#define GSMEM_C (3*CSTAGE)           // 92160

template <int TAPS>
__global__ __launch_bounds__(256, 1) void gemm_conv(
    const __nv_bfloat16* __restrict__ W, float* __restrict__ C,
    const float* __restrict__ bias)
{
    extern __shared__ char sm_[];
    uint32_t smb = smem_u32(sm_);
    int tid = threadIdx.x, lane = tid & 31, wid = tid >> 5;
    int wm = wid >> 1, wn = wid & 1;
    int b = blockIdx.z;
    int n0 = blockIdx.x * 128;
    const int Kp = TAPS * 768;
    const int nk = TAPS * 24;
    const __nv_bfloat16* XH = g_xt_h + (size_t)b * 4356 * 256;
    const __nv_bfloat16* XL = g_xt_l + (size_t)b * 4356 * 256;

    auto load = [&](int kt) {
        int st = kt % 3;
        uint32_t as = smb + st * CSTAGE;
        uint32_t bs = smb + st * CSTAGE + 256 * STR;
        int blk = kt / (TAPS * 8);
        int rem = kt - blk * (TAPS * 8);
        int t = rem >> 3, c0 = (rem & 7) << 5;
        int dy = (TAPS == 9) ? t / 3 : 1;
        int dx = (TAPS == 9) ? t % 3 : 1;
        const __nv_bfloat16* buf = (blk == 1) ? XL : XH;
#pragma unroll
        for (int u = 0; u < 4; u++) {       // A: 256 rows x 4 chunks
            int e = tid + u * 256;
            int row = e >> 2, ch = e & 3;
            cpa16(as + row * STR + ch * 16, W + (size_t)row * Kp + kt * 32 + ch * 8);
        }
#pragma unroll
        for (int u = 0; u < 2; u++) {       // B: 128 rows x 4 chunks
            int e = tid + u * 256;
            int row = e >> 2, ch = e & 3;
            int p = n0 + row, y = p >> 6, xx = p & 63;
            cpa16(bs + row * STR + ch * 16,
                  buf + (size_t)((y + dy) * 66 + (xx + dx)) * 256 + c0 + ch * 8);
        }
        asm volatile("cp.async.commit_group;" ::: "memory");
    };

    float acc[4][8][4];
#pragma unroll
    for (int i = 0; i < 4; i++)
#pragma unroll
        for (int j = 0; j < 8; j++)
#pragma unroll
            for (int r = 0; r < 4; r++) acc[i][j][r] = 0.f;

    load(0);
    load(1);
    for (int kt = 0; kt < nk; kt++) {
        asm volatile("cp.async.wait_group 1;" ::: "memory");
        __syncthreads();
        int st = kt % 3;
        uint32_t as = smb + st * CSTAGE + (wm * 64 + (lane & 15)) * STR + (lane >> 4) * 16;
        uint32_t bs = smb + st * CSTAGE + 256 * STR + (wn * 64 + (lane & 15)) * STR + (lane >> 4) * 16;
#pragma unroll
        for (int kk = 0; kk < 2; kk++) {
            uint32_t a[4][4], bb[4][4];
#pragma unroll
            for (int mt = 0; mt < 4; mt++) ldm4(a[mt], as + mt * 16 * STR + kk * 32);
#pragma unroll
            for (int nt = 0; nt < 4; nt++) ldm4(bb[nt], bs + nt * 16 * STR + kk * 32);
#pragma unroll
            for (int mt = 0; mt < 4; mt++)
#pragma unroll
                for (int n8 = 0; n8 < 8; n8++)
                    mma16(acc[mt][n8], a[mt], bb[n8 >> 1][n8 & 1], bb[n8 >> 1][(n8 & 1) + 2]);
        }
        __syncthreads();
        if (kt + 2 < nk) load(kt + 2);
        else asm volatile("cp.async.commit_group;" ::: "memory");
    }

    float* Cb = C + (size_t)b * NC * NPIX;
#pragma unroll
    for (int mt = 0; mt < 4; mt++) {
        int row = wm * 64 + mt * 16 + (lane >> 2);
        float bi0 = bias[row], bi1 = bias[row + 8];
#pragma unroll
        for (int n8 = 0; n8 < 8; n8++) {
            int col = n0 + wn * 64 + n8 * 8 + (lane & 3) * 2;
            float2 v0, v1;
            v0.x = acc[mt][n8][0] + bi0; v0.y = acc[mt][n8][1] + bi0;
            v1.x = acc[mt][n8][2] + bi1; v1.y = acc[mt][n8][3] + bi1;
            *(float2*)&Cb[(size_t)row * 4096 + col] = v0;
            *(float2*)&Cb[(size_t)(row + 8) * 4096 + col] = v1;
        }
    }
}

// ---------------------------------------------------------------------------
// S GEMM (unchanged R5 core, MODE1): S[q][k] = sum Qth[q][:] Kth[k][:]
// ---------------------------------------------------------------------------
#define SSTAGE (128*STR)
#define GSMEM_S (6*SSTAGE)

__global__ __launch_bounds__(256, 1) void gemm_s(
    const __nv_bfloat16* __restrict__ A, const __nv_bfloat16* __restrict__ B,
    float* __restrict__ C)
{
    extern __shared__ char sm_[];
    uint32_t smb = smem_u32(sm_);
    int tid = threadIdx.x, lane = tid & 31, wid = tid >> 5;
    int wm = wid & 1, wn = wid >> 1;
    int bz = blockIdx.z;
    int m0 = blockIdx.y * 128, n0 = blockIdx.x * 128;
    const __nv_bfloat16* Ab = A + (size_t)bz * 4096 * 768 + (size_t)m0 * 768;
    const __nv_bfloat16* Bb = B + (size_t)bz * 4096 * 768 + (size_t)n0 * 768;
    const int nk = 24;

    auto load = [&](int kt) {
        int st = kt % 3;
        uint32_t as = smb + st * SSTAGE;
        uint32_t bs = smb + 3 * SSTAGE + st * SSTAGE;
        int k0 = kt * 32;
#pragma unroll
        for (int i = 0; i < 2; i++) {
            int e = tid + i * 256;
            int row = e >> 2, ch = e & 3;
            cpa16(as + row * STR + ch * 16, Ab + (size_t)row * 768 + k0 + ch * 8);
            cpa16(bs + row * STR + ch * 16, Bb + (size_t)row * 768 + k0 + ch * 8);
        }
        asm volatile("cp.async.commit_group;" ::: "memory");
    };

    float acc[4][4][4];
#pragma unroll
    for (int i = 0; i < 4; i++)
#pragma unroll
        for (int j = 0; j < 4; j++)
#pragma unroll
            for (int r = 0; r < 4; r++) acc[i][j][r] = 0.f;

    load(0);
    load(1);
    for (int kt = 0; kt < nk; kt++) {
        asm volatile("cp.async.wait_group 1;" ::: "memory");
        __syncthreads();
        int st = kt % 3;
        uint32_t as = smb + st * SSTAGE + (wm * 64 + (lane & 15)) * STR + (lane >> 4) * 16;
        uint32_t bs = smb + 3 * SSTAGE + st * SSTAGE + (wn * 32 + (lane & 15)) * STR + (lane >> 4) * 16;
#pragma unroll
        for (int kk = 0; kk < 2; kk++) {
            uint32_t a[4][4], bb[2][4];
#pragma unroll
            for (int mt = 0; mt < 4; mt++) ldm4(a[mt], as + mt * 16 * STR + kk * 32);
#pragma unroll
            for (int nt = 0; nt < 2; nt++) ldm4(bb[nt], bs + nt * 16 * STR + kk * 32);
#pragma unroll
            for (int mt = 0; mt < 4; mt++)
#pragma unroll
                for (int n8 = 0; n8 < 4; n8++)
                    mma16(acc[mt][n8], a[mt], bb[n8 >> 1][n8 & 1], bb[n8 >> 1][(n8 & 1) + 2]);
        }
        __syncthreads();
        if (kt + 2 < nk) load(kt + 2);
        else asm volatile("cp.async.commit_group;" ::: "memory");
    }

    float* Cb = C + (size_t)bz * 4096 * 4096;
#pragma unroll
    for (int mt = 0; mt < 4; mt++) {
        int row = m0 + wm * 64 + mt * 16 + (lane >> 2);
#pragma unroll
        for (int n8 = 0; n8 < 4; n8++) {
            int col = n0 + wn * 32 + n8 * 8 + (lane & 3) * 2;
            float2 v0, v1;
            v0.x = acc[mt][n8][0]; v0.y = acc[mt][n8][1];
            v1.x = acc[mt][n8][2]; v1.y = acc[mt][n8][3];
            *(float2*)&Cb[(size_t)row * 4096 + col] = v0;
            *(float2*)&Cb[(size_t)(row + 8) * 4096 + col] = v1;
        }
    }
}

// ---------------------------------------------------------------------------
// Fused O GEMM: out[c][q] = sum_k V[c][k] * exp(S[q][k]-m[q])*iz[q]  (+bw[q]*vbv[c])
// BM=256 (all c), BN=128 q, BK=32 keys, 3 bf16 terms: vh*ph + vh*pl + vl*ph.
// A (vh|vl) cp.async 3-stage; B: LDG S fp32 -> exp/split -> STS double buffer.
// ---------------------------------------------------------------------------
#define OASTG (2*256*STR)                 // 40960 per A stage (vh+vl)
#define OB0   (3*OASTG)                   // 122880
#define OBSTG (2*128*STR)                 // 20480 per B buffer (ph+pl)
#define GSMEM_O (OB0 + 2*OBSTG)           // 163840

__global__ __launch_bounds__(256, 1) void gemm_o(float* __restrict__ Cout)
{
    extern __shared__ char sm_[];
    uint32_t smb = smem_u32(sm_);
    int tid = threadIdx.x, lane = tid & 31, wid = tid >> 5;
    int wm = wid >> 1, wn = wid & 1;
    int b = blockIdx.z;
    int n0 = blockIdx.x * 128;
    const __nv_bfloat16* Vb = g_vh2 + (size_t)b * 2 * NC * NPIX;
    const int nk = 128;

    int brow = tid >> 1, half = tid & 1;
    int q = n0 + brow;
    float mq = g_m[b * 4096 + q];
    float izq = g_iz[b * 4096 + q];
    const float* Sg = g_S + ((size_t)b * 4096 + q) * 4096 + half * 16;

    auto loadA = [&](int kt) {
        int st = kt % 3;
#pragma unroll
        for (int u = 0; u < 8; u++) {
            int e = tid + u * 256;
            int ts = e >> 10;            // 0: vh, 1: vl
            int e2 = e & 1023;
            int row = e2 >> 2, ch = e2 & 3;
            cpa16(smb + st * OASTG + ts * (256 * STR) + row * STR + ch * 16,
                  Vb + ((size_t)ts * NC + row) * 4096 + kt * 32 + ch * 8);
        }
        asm volatile("cp.async.commit_group;" ::: "memory");
    };

    float acc[4][8][4];
#pragma unroll
    for (int i = 0; i < 4; i++)
#pragma unroll
        for (int j = 0; j < 8; j++)
#pragma unroll
            for (int r = 0; r < 4; r++) acc[i][j][r] = 0.f;

    float4 f[4];
    loadA(0);
    loadA(1);
#pragma unroll
    for (int i = 0; i < 4; i++) f[i] = ((const float4*)Sg)[i];

    for (int kt = 0; kt < nk; kt++) {
        asm volatile("cp.async.wait_group 1;" ::: "memory");
        __syncthreads();
        // convert + STS B(kt)
        {
            float e16[16];
            float* fp = (float*)f;
#pragma unroll
            for (int j = 0; j < 16; j++) e16[j] = fexp(fp[j] - mq) * izq;
            __nv_bfloat16 hh[16], ll[16];
#pragma unroll
            for (int j = 0; j < 16; j++) split2(e16[j], hh[j], ll[j]);
            int b2 = kt & 1;
            char* bp = sm_ + OB0 + b2 * OBSTG + brow * STR + half * 32;
            *(uint4*)bp = ((uint4*)hh)[0];
            *(uint4*)(bp + 16) = ((uint4*)hh)[1];
            *(uint4*)(bp + 128 * STR) = ((uint4*)ll)[0];
            *(uint4*)(bp + 128 * STR + 16) = ((uint4*)ll)[1];
        }
        if (kt + 1 < nk) {
            const float4* s4 = (const float4*)(Sg + (kt + 1) * 32);
#pragma unroll
            for (int i = 0; i < 4; i++) f[i] = s4[i];
        }
        if (kt + 2 < nk) loadA(kt + 2);
        else asm volatile("cp.async.commit_group;" ::: "memory");
        __syncthreads();

        int st = kt % 3, b2 = kt & 1;
        uint32_t ash = smb + st * OASTG + (wm * 64 + (lane & 15)) * STR + (lane >> 4) * 16;
        uint32_t asl = ash + 256 * STR;
        uint32_t bsp = smb + OB0 + b2 * OBSTG + (wn * 64 + (lane & 15)) * STR + (lane >> 4) * 16;
        uint32_t bsl = bsp + 128 * STR;
#pragma unroll
        for (int kk = 0; kk < 2; kk++) {
            uint32_t ah[4][4], al[4][4], bh[4][4], bl[4][4];
#pragma unroll
            for (int mt = 0; mt < 4; mt++) ldm4(ah[mt], ash + mt * 16 * STR + kk * 32);
#pragma unroll
            for (int nt = 0; nt < 4; nt++) ldm4(bh[nt], bsp + nt * 16 * STR + kk * 32);
#pragma unroll
            for (int mt = 0; mt < 4; mt++)
#pragma unroll
                for (int n8 = 0; n8 < 8; n8++)
                    mma16(acc[mt][n8], ah[mt], bh[n8 >> 1][n8 & 1], bh[n8 >> 1][(n8 & 1) + 2]);
#pragma unroll
            for (int nt = 0; nt < 4; nt++) ldm4(bl[nt], bsl + nt * 16 * STR + kk * 32);
#pragma unroll
            for (int mt = 0; mt < 4; mt++)
#pragma unroll
                for (int n8 = 0; n8 < 8; n8++)
                    mma16(acc[mt][n8], ah[mt], bl[n8 >> 1][n8 & 1], bl[n8 >> 1][(n8 & 1) + 2]);
#pragma unroll
            for (int mt = 0; mt < 4; mt++) ldm4(al[mt], asl + mt * 16 * STR + kk * 32);
#pragma unroll
            for (int mt = 0; mt < 4; mt++)
#pragma unroll
                for (int n8 = 0; n8 < 8; n8++)
                    mma16(acc[mt][n8], al[mt], bh[n8 >> 1][n8 & 1], bh[n8 >> 1][(n8 & 1) + 2]);
        }
    }

    float* Cb = Cout + (size_t)b * NC * NPIX;
    const float* bwp = g_bw + (size_t)b * 4096;
#pragma unroll
    for (int mt = 0; mt < 4; mt++) {
        int row = wm * 64 + mt * 16 + (lane >> 2);
        float vb0 = g_vbv[row], vb1 = g_vbv[row + 8];
#pragma unroll
        for (int n8 = 0; n8 < 8; n8++) {
            int col = n0 + wn * 64 + n8 * 8 + (lane & 3) * 2;
            float w0 = bwp[col], w1 = bwp[col + 1];
            float2 v0, v1;
            v0.x = fmaf(w0, vb0, acc[mt][n8][0]); v0.y = fmaf(w1, vb0, acc[mt][n8][1]);
            v1.x = fmaf(w0, vb1, acc[mt][n8][2]); v1.y = fmaf(w1, vb1, acc[mt][n8][3]);
            *(float2*)&Cb[(size_t)row * 4096 + col] = v0;
            *(float2*)&Cb[(size_t)(row + 8) * 4096 + col] = v1;
        }
    }
}

// ---- prep kernels ----
__global__ void zero_k(uint4* p, int n) {
    int i = blockIdx.x * 256 + threadIdx.x;
    if (i < n) p[i] = make_uint4(0, 0, 0, 0);
}

// fill xt interior: x[b][c][p] -> xt_h/l[b][(y+1)*66+x+1][c]
__global__ void xt_fill(const float* __restrict__ x) {
    __shared__ float tile[32][33];
    int b = blockIdx.z;
    int p0 = blockIdx.x * 32, c0 = blockIdx.y * 32;
    int tx = threadIdx.x, ty = threadIdx.y;   // 32x8
    const float* s = x + (size_t)b * NC * NPIX;
    for (int j = 0; j < 32; j += 8)
        tile[ty + j][tx] = s[(size_t)(c0 + ty + j) * NPIX + p0 + tx];
    __syncthreads();
    for (int j = 0; j < 32; j += 8) {
        int p = p0 + ty + j, y = p >> 6, xx = p & 63;
        size_t o = ((size_t)b * 4356 + (y + 1) * 66 + (xx + 1)) * 256 + c0 + tx;
        __nv_bfloat16 h, l;
        split2(tile[tx][ty + j], h, l);
        g_xt_h[o] = h;
        g_xt_l[o] = l;
    }
}

// Wq split + permute: k' ordering t*256+c, blocks [h,h,l]
__global__ void wsplit_q(const float* __restrict__ w) {
    int idx = blockIdx.x * 256 + threadIdx.x;
    if (idx >= NC * 2304) return;
    int m = idx / 2304, r = idx % 2304;
    int c = r / 9, t = r % 9;
    __nv_bfloat16 h, l;
    split2(w[idx], h, l);
    size_t base = (size_t)m * 6912 + t * 256 + c;
    g_wqh[base] = h; g_wqh[base + 2304] = h; g_wqh[base + 4608] = l;
}

// 1x1 weights: A-pattern [h,h,l], k'=blk*256+c
__global__ void wsplit1(const float* __restrict__ w, __nv_bfloat16* __restrict__ o) {
    int idx = blockIdx.x * 256 + threadIdx.x;
    if (idx >= NC * NC) return;
    int m = idx / NC, c = idx % NC;
    __nv_bfloat16 h, l;
    split2(w[idx], h, l);
    size_t base = (size_t)m * 768 + c;
    o[base] = h; o[base + 256] = h; o[base + 512] = l;
}

// transpose [c][pix] -> [pix][c3] with affine; patA:[h,h,l] else [h,l,h]
__global__ void tsplit(const float* __restrict__ src, __nv_bfloat16* __restrict__ dst,
                       const float* __restrict__ aa, const float* __restrict__ ad, int patA) {
    __shared__ float tile[32][33];
    int b = blockIdx.z;
    int p0 = blockIdx.x * 32, c0 = blockIdx.y * 32;
    int tx = threadIdx.x, ty = threadIdx.y;
    const float* s = src + (size_t)b * NC * NPIX;
    for (int j = 0; j < 32; j += 8) {
        float a = aa[c0 + ty + j], d = ad[c0 + ty + j];
        tile[ty + j][tx] = fmaf(a, s[(size_t)(c0 + ty + j) * NPIX + p0 + tx], d);
    }
    __syncthreads();
    for (int j = 0; j < 32; j += 8) {
        __nv_bfloat16 h, l;
        split2(tile[tx][ty + j], h, l);
        __nv_bfloat16* o = dst + ((size_t)b * 4096 + p0 + ty + j) * 768 + c0 + tx;
        o[0] = h;
        o[256] = patA ? h : l;
        o[512] = patA ? l : h;
    }
}

// V affine + split -> vh2 [b][hl][c][k]
__global__ void vhl_k() {
    size_t i4 = (size_t)blockIdx.x * 256 + threadIdx.x;
    size_t e = i4 * 4;
    int c = (int)((e >> 12) & 255);
    int b = (int)(e >> 20);
    int k = (int)(e & 4095);
    float a = g_a[512 + c], d = g_dd[512 + c];
    float4 v = *(float4*)(g_vc + e);
    __nv_bfloat16 h[4], l[4];
    split2(fmaf(a, v.x, d), h[0], l[0]);
    split2(fmaf(a, v.y, d), h[1], l[1]);
    split2(fmaf(a, v.z, d), h[2], l[2]);
    split2(fmaf(a, v.w, d), h[3], l[3]);
    *(uint2*)(g_vh2 + ((size_t)(b * 2 + 0) * 256 + c) * 4096 + k) = *(uint2*)h;
    *(uint2*)(g_vh2 + ((size_t)(b * 2 + 1) * 256 + c) * 4096 + k) = *(uint2*)l;
}

__global__ void stats_k(const float* __restrict__ bq, const float* __restrict__ gq, const float* __restrict__ betaq,
                        const float* __restrict__ bk, const float* __restrict__ gk, const float* __restrict__ betak,
                        const float* __restrict__ bv, const float* __restrict__ gv, const float* __restrict__ betav)
{
    int c = blockIdx.x, t = blockIdx.y;
    const float* src = (t == 0) ? g_qc : (t == 1) ? g_kc : g_vc;
    int tid = threadIdx.x;
    float s1 = 0.f, s2 = 0.f;
    for (int b = 0; b < NB; b++) {
        const float* p = src + ((size_t)b * NC + c) * NPIX;
        for (int i = tid; i < NPIX; i += 256) {
            float v = p[i];
            s1 += v; s2 += v * v;
        }
    }
    __shared__ double r1[256], r2[256];
    r1[tid] = s1; r2[tid] = s2;
    __syncthreads();
    for (int s = 128; s > 0; s >>= 1) {
        if (tid < s) { r1[tid] += r1[tid + s]; r2[tid] += r2[tid + s]; }
        __syncthreads();
    }
    if (tid == 0) {
        double S1 = r1[0], S2 = r2[0], cnt = 16384.0;
        float bias = (t == 0) ? bq[c] : (t == 1) ? bk[c] : bv[c];
        float g    = (t == 0) ? gq[c] : (t == 1) ? gk[c] : gv[c];
        float be   = (t == 0) ? betaq[c] : (t == 1) ? betak[c] : betav[c];
        if (t > 0) {
            cnt = 17424.0;
            S1 += 1040.0 * (double)bias;
            S2 += 1040.0 * (double)bias * (double)bias;
        }
        double mean = S1 / cnt;
        double var = S2 / cnt - mean * mean;
        float a = g * rsqrtf((float)var + 1e-5f);
        float d = be - a * (float)mean;
        g_a[t * NC + c] = a;
        g_dd[t * NC + c] = d;
        if (t == 1) g_kbv[c] = fmaf(a, bias, d);
        if (t == 2) g_vbv[c] = fmaf(a, bias, d);
    }
}

__global__ void sb_k() {
    int b = blockIdx.y;
    int q = blockIdx.x * 256 + threadIdx.x;
    const float* Q = g_qc + (size_t)b * NC * NPIX;
    float s = 0.f;
#pragma unroll 8
    for (int c = 0; c < NC; c++) {
        float qn = fmaf(g_a[c], Q[(size_t)c * NPIX + q], g_dd[c]);
        s = fmaf(g_kbv[c], qn, s);
    }
    g_sb[b * NPIX + q] = s;
}

// softmax-lite: per row compute m, iz, bw only
__global__ __launch_bounds__(256) void softmax_lite() {
    int row = blockIdx.x;
    int t = threadIdx.x;
    const float4* Sp = (const float4*)(g_S + (size_t)row * 4096);
    float4 v[4];
    float m = -3.4e38f;
#pragma unroll
    for (int j = 0; j < 4; j++) {
        v[j] = Sp[t * 4 + j];
        m = fmaxf(m, fmaxf(fmaxf(v[j].x, v[j].y), fmaxf(v[j].z, v[j].w)));
    }
    __shared__ float red[256];
    red[t] = m;
    __syncthreads();
    for (int s = 128; s > 0; s >>= 1) {
        if (t < s) red[t] = fmaxf(red[t], red[t + s]);
        __syncthreads();
    }
    float sbv = g_sb[row];
    m = fmaxf(red[0], sbv);
    __syncthreads();
    float s = 0.f;
#pragma unroll
    for (int j = 0; j < 4; j++)
        s += fexp(v[j].x - m) + fexp(v[j].y - m) + fexp(v[j].z - m) + fexp(v[j].w - m);
    red[t] = s;
    __syncthreads();
    for (int st = 128; st > 0; st >>= 1) {
        if (t < st) red[t] += red[t + st];
        __syncthreads();
    }
    if (t == 0) {
        float eb = 260.f * fexp(sbv - m);
        float iz = 1.f / (red[0] + eb);
        g_bw[row] = eb * iz;
        g_m[row] = m;
        g_iz[row] = iz;
    }
}

// ---------------------------------------------------------------------------
extern "C" void kernel_launch(void* const* d_in, const int* in_sizes, int n_in,
                              void* d_out, int out_size)
{
    const float* x     = (const float*)d_in[0];
    const float* Wq    = (const float*)d_in[1];
    const float* bq    = (const float*)d_in[2];
    const float* gq    = (const float*)d_in[3];
    const float* betaq = (const float*)d_in[4];
    const float* Wk    = (const float*)d_in[5];
    const float* bk    = (const float*)d_in[6];
    const float* gk    = (const float*)d_in[7];
    const float* betak = (const float*)d_in[8];
    const float* Wv    = (const float*)d_in[9];
    const float* bv    = (const float*)d_in[10];
    const float* gv    = (const float*)d_in[11];
    const float* betav = (const float*)d_in[12];
    float* out = (float*)d_out;

    cudaFuncSetAttribute(gemm_conv<9>, cudaFuncAttributeMaxDynamicSharedMemorySize, GSMEM_C);
    cudaFuncSetAttribute(gemm_conv<1>, cudaFuncAttributeMaxDynamicSharedMemorySize, GSMEM_C);
    cudaFuncSetAttribute(gemm_s, cudaFuncAttributeMaxDynamicSharedMemorySize, GSMEM_S);
    cudaFuncSetAttribute(gemm_o, cudaFuncAttributeMaxDynamicSharedMemorySize, GSMEM_O);

    __nv_bfloat16 *p_xth, *p_xtl, *p_wkh, *p_wvh, *p_qth, *p_kth;
    float *p_qc, *p_kc, *p_vc, *p_S, *p_a, *p_dd;
    cudaGetSymbolAddress((void**)&p_xth, g_xt_h);
    cudaGetSymbolAddress((void**)&p_xtl, g_xt_l);
    cudaGetSymbolAddress((void**)&p_wkh, g_wkh);
    cudaGetSymbolAddress((void**)&p_wvh, g_wvh);
    cudaGetSymbolAddress((void**)&p_qth, g_qth);
    cudaGetSymbolAddress((void**)&p_kth, g_kth);
    cudaGetSymbolAddress((void**)&p_qc,  g_qc);
    cudaGetSymbolAddress((void**)&p_kc,  g_kc);
    cudaGetSymbolAddress((void**)&p_vc,  g_vc);
    cudaGetSymbolAddress((void**)&p_S,   g_S);
    cudaGetSymbolAddress((void**)&p_a,   g_a);
    cudaGetSymbolAddress((void**)&p_dd,  g_dd);

    __nv_bfloat16 *p_wqh;
    cudaGetSymbolAddress((void**)&p_wqh, g_wqh);

    // 1. padded transposed hi/lo x + weight splits
    int nz = (int)(((size_t)NB * 4356 * 256 * 2 / 16 + 255) / 256);
    zero_k<<<nz, 256>>>((uint4*)p_xth, (int)((size_t)NB * 4356 * 256 * 2 / 16));
    zero_k<<<nz, 256>>>((uint4*)p_xtl, (int)((size_t)NB * 4356 * 256 * 2 / 16));
    xt_fill<<<dim3(128, 8, NB), dim3(32, 8)>>>(x);
    wsplit_q<<<(NC * 2304 + 255) / 256, 256>>>(Wq);
    wsplit1<<<(NC * NC + 255) / 256, 256>>>(Wk, p_wkh);
    wsplit1<<<(NC * NC + 255) / 256, 256>>>(Wv, p_wvh);

    // 2. convs (implicit im2col)
    gemm_conv<9><<<dim3(32, 1, NB), 256, GSMEM_C>>>(p_wqh, p_qc, bq);
    gemm_conv<1><<<dim3(32, 1, NB), 256, GSMEM_C>>>(p_wkh, p_kc, bk);
    gemm_conv<1><<<dim3(32, 1, NB), 256, GSMEM_C>>>(p_wvh, p_vc, bv);

    // 3. BN stats + splits + border scores
    stats_k<<<dim3(256, 3), 256>>>(bq, gq, betaq, bk, gk, betak, bv, gv, betav);
    tsplit<<<dim3(128, 8, NB), dim3(32, 8)>>>(p_qc, p_qth, p_a, p_dd, 1);
    tsplit<<<dim3(128, 8, NB), dim3(32, 8)>>>(p_kc, p_kth, p_a + 256, p_dd + 256, 0);
    vhl_k<<<(int)(((size_t)NB * NC * NPIX / 4) / 256), 256>>>();
    sb_k<<<dim3(16, NB), 256>>>();

    // 4. S[q][k]
    gemm_s<<<dim3(32, 32, NB), 256, GSMEM_S>>>(p_qth, p_kth, p_S);

    // 5. softmax stats only
    softmax_lite<<<NB * NPIX, 256>>>();

    // 6. fused O GEMM (exp/split in-kernel)
    gemm_o<<<dim3(32, 1, NB), 256, GSMEM_O>>>(out);
}

// round 7
// speedup vs baseline: 1.8371x; 1.0359x over previous
#include <cuda_runtime.h>
#include <cuda_bf16.h>
#include <math.h>
#include <stdint.h>

#define NB 4
#define NC 256
#define NPIX 4096
#define STR 80

// ---- static device scratch ----
__device__ __nv_bfloat16 g_xt_h[(size_t)NB*4356*256];   // padded x, [b][pix66][c] hi
__device__ __nv_bfloat16 g_xt_l[(size_t)NB*4356*256];   // lo
__device__ __nv_bfloat16 g_wqh[NC*6912];                // Wq split, A-pat [h,h,l], k=t*256+c
__device__ __nv_bfloat16 g_wkh[NC*768];
__device__ __nv_bfloat16 g_wvh[NC*768];
__device__ float g_qc[(size_t)NB*NC*NPIX];
__device__ float g_kc[(size_t)NB*NC*NPIX];
__device__ float g_vc[(size_t)NB*NC*NPIX];
__device__ __nv_bfloat16 g_qth[(size_t)NB*NPIX*768];    // BN(Q)^T, A-pat
__device__ __nv_bfloat16 g_kth[(size_t)NB*NPIX*768];    // BN(K)^T, B-pat
__device__ __nv_bfloat16 g_vh2[(size_t)NB*2*NC*NPIX];   // BN(V) hi | lo, [b][hl][c][k]
__device__ float g_S[(size_t)NB*NPIX*NPIX];             // scores [b][q][k]
__device__ float g_pm[(size_t)NB*32*NPIX];              // per-tile max  [b][t][q]
__device__ float g_ps[(size_t)NB*32*NPIX];              // per-tile sum  [b][t][q]
__device__ float g_sb[NB*NPIX];
__device__ float g_bw[NB*NPIX];
__device__ float g_m[NB*NPIX];
__device__ float g_iz[NB*NPIX];
__device__ float g_a[3*NC];
__device__ float g_dd[3*NC];
__device__ float g_kbv[NC];
__device__ float g_vbv[NC];

// ---- helpers ----
__device__ __forceinline__ uint32_t smem_u32(const void* p) {
    uint32_t a;
    asm("{ .reg .u64 t; cvta.to.shared.u64 t, %1; cvt.u32.u64 %0, t; }" : "=r"(a) : "l"(p));
    return a;
}
__device__ __forceinline__ void cpa16(uint32_t s, const void* g) {
    asm volatile("cp.async.cg.shared.global [%0], [%1], 16;" :: "r"(s), "l"(g));
}
__device__ __forceinline__ void ldm4(uint32_t* r, uint32_t addr) {
    asm volatile("ldmatrix.sync.aligned.m8n8.x4.shared.b16 {%0,%1,%2,%3}, [%4];"
                 : "=r"(r[0]), "=r"(r[1]), "=r"(r[2]), "=r"(r[3]) : "r"(addr));
}
__device__ __forceinline__ void mma16(float* d, const uint32_t* a, uint32_t b0, uint32_t b1) {
    asm volatile(
        "mma.sync.aligned.m16n8k16.row.col.f32.bf16.bf16.f32 "
        "{%0,%1,%2,%3}, {%4,%5,%6,%7}, {%8,%9}, {%0,%1,%2,%3};"
        : "+f"(d[0]), "+f"(d[1]), "+f"(d[2]), "+f"(d[3])
        : "r"(a[0]), "r"(a[1]), "r"(a[2]), "r"(a[3]), "r"(b0), "r"(b1));
}
__device__ __forceinline__ float fexp(float x) {
    x = fmaxf(x, -87.0f);
    float t = fmaf(x, 1.4426950408889634f, 12582912.0f);
    float i = t - 12582912.0f;
    float f = fmaf(x, 1.4426950408889634f, -i);
    float y = f * 0.6931471805599453f;
    float p = fmaf(y, 0.0083333338f, 0.041666668f);
    p = fmaf(y, p, 0.16666667f);
    p = fmaf(y, p, 0.5f);
    p = fmaf(y, p, 1.0f);
    p = fmaf(y, p, 1.0f);
    return p * __int_as_float(((int)i + 127) << 23);
}
__device__ __forceinline__ void split2(float v, __nv_bfloat16& h, __nv_bfloat16& l) {
    h = __float2bfloat16(v);
    l = __float2bfloat16(v - __bfloat162float(h));
}

// ---------------------------------------------------------------------------
// Implicit-im2col conv GEMM: C[m=oc][n=pix] = sum_k' W[m][k'] * xt[pix,k']
// BM=128, BN=128, BK=32. 8 warps 2x4, warp tile 64x32. occ target 2 CTA/SM.
// ---------------------------------------------------------------------------
#define CSTAGE (2*128*STR)           // 20480 (A 128 rows + B 128 rows)
#define GSMEM_C (3*CSTAGE)           // 61440

template <int TAPS>
__global__ __launch_bounds__(256, 2) void gemm_conv(
    const __nv_bfloat16* __restrict__ W, float* __restrict__ C,
    const float* __restrict__ bias)
{
    extern __shared__ char sm_[];
    uint32_t smb = smem_u32(sm_);
    int tid = threadIdx.x, lane = tid & 31, wid = tid >> 5;
    int wm = wid & 1, wn = wid >> 1;
    int b = blockIdx.z;
    int m0 = blockIdx.y * 128, n0 = blockIdx.x * 128;
    const int Kp = TAPS * 768;
    const int nk = TAPS * 24;
    const __nv_bfloat16* XH = g_xt_h + (size_t)b * 4356 * 256;
    const __nv_bfloat16* XL = g_xt_l + (size_t)b * 4356 * 256;
    const __nv_bfloat16* Wb = W + (size_t)m0 * Kp;

    auto load = [&](int kt) {
        int st = kt % 3;
        uint32_t as = smb + st * CSTAGE;
        uint32_t bs = smb + st * CSTAGE + 128 * STR;
        int blk = kt / (TAPS * 8);
        int rem = kt - blk * (TAPS * 8);
        int t = rem >> 3, c0 = (rem & 7) << 5;
        int dy = (TAPS == 9) ? t / 3 : 1;
        int dx = (TAPS == 9) ? t % 3 : 1;
        const __nv_bfloat16* buf = (blk == 1) ? XL : XH;
#pragma unroll
        for (int u = 0; u < 2; u++) {
            int e = tid + u * 256;
            int row = e >> 2, ch = e & 3;
            cpa16(as + row * STR + ch * 16, Wb + (size_t)row * Kp + kt * 32 + ch * 8);
        }
#pragma unroll
        for (int u = 0; u < 2; u++) {
            int e = tid + u * 256;
            int row = e >> 2, ch = e & 3;
            int p = n0 + row, y = p >> 6, xx = p & 63;
            cpa16(bs + row * STR + ch * 16,
                  buf + (size_t)((y + dy) * 66 + (xx + dx)) * 256 + c0 + ch * 8);
        }
        asm volatile("cp.async.commit_group;" ::: "memory");
    };

    float acc[4][4][4];
#pragma unroll
    for (int i = 0; i < 4; i++)
#pragma unroll
        for (int j = 0; j < 4; j++)
#pragma unroll
            for (int r = 0; r < 4; r++) acc[i][j][r] = 0.f;

    load(0);
    load(1);
    for (int kt = 0; kt < nk; kt++) {
        asm volatile("cp.async.wait_group 1;" ::: "memory");
        __syncthreads();
        int st = kt % 3;
        uint32_t as = smb + st * CSTAGE + (wm * 64 + (lane & 15)) * STR + (lane >> 4) * 16;
        uint32_t bs = smb + st * CSTAGE + 128 * STR + (wn * 32 + (lane & 15)) * STR + (lane >> 4) * 16;
#pragma unroll
        for (int kk = 0; kk < 2; kk++) {
            uint32_t a[4][4], bb[2][4];
#pragma unroll
            for (int mt = 0; mt < 4; mt++) ldm4(a[mt], as + mt * 16 * STR + kk * 32);
#pragma unroll
            for (int nt = 0; nt < 2; nt++) ldm4(bb[nt], bs + nt * 16 * STR + kk * 32);
#pragma unroll
            for (int mt = 0; mt < 4; mt++)
#pragma unroll
                for (int n8 = 0; n8 < 4; n8++)
                    mma16(acc[mt][n8], a[mt], bb[n8 >> 1][n8 & 1], bb[n8 >> 1][(n8 & 1) + 2]);
        }
        __syncthreads();
        if (kt + 2 < nk) load(kt + 2);
        else asm volatile("cp.async.commit_group;" ::: "memory");
    }

    float* Cb = C + (size_t)b * NC * NPIX;
#pragma unroll
    for (int mt = 0; mt < 4; mt++) {
        int row = m0 + wm * 64 + mt * 16 + (lane >> 2);
        float bi0 = bias[row], bi1 = bias[row + 8];
#pragma unroll
        for (int n8 = 0; n8 < 4; n8++) {
            int col = n0 + wn * 32 + n8 * 8 + (lane & 3) * 2;
            float2 v0, v1;
            v0.x = acc[mt][n8][0] + bi0; v0.y = acc[mt][n8][1] + bi0;
            v1.x = acc[mt][n8][2] + bi1; v1.y = acc[mt][n8][3] + bi1;
            *(float2*)&Cb[(size_t)row * 4096 + col] = v0;
            *(float2*)&Cb[(size_t)(row + 8) * 4096 + col] = v1;
        }
    }
}

// ---------------------------------------------------------------------------
// S GEMM + fused partial softmax stats.
// S[q][k] = sum Qth[q][:] Kth[k][:]; per-CTA per-q (max, sum-exp) partials.
// ---------------------------------------------------------------------------
#define SSTAGE (128*STR)
#define GSMEM_S (6*SSTAGE)

__global__ __launch_bounds__(256, 2) void gemm_s(
    const __nv_bfloat16* __restrict__ A, const __nv_bfloat16* __restrict__ B,
    float* __restrict__ C)
{
    extern __shared__ char sm_[];
    uint32_t smb = smem_u32(sm_);
    int tid = threadIdx.x, lane = tid & 31, wid = tid >> 5;
    int wm = wid & 1, wn = wid >> 1;
    int bz = blockIdx.z;
    int m0 = blockIdx.y * 128, n0 = blockIdx.x * 128;
    const __nv_bfloat16* Ab = A + (size_t)bz * 4096 * 768 + (size_t)m0 * 768;
    const __nv_bfloat16* Bb = B + (size_t)bz * 4096 * 768 + (size_t)n0 * 768;
    const int nk = 24;

    auto load = [&](int kt) {
        int st = kt % 3;
        uint32_t as = smb + st * SSTAGE;
        uint32_t bs = smb + 3 * SSTAGE + st * SSTAGE;
        int k0 = kt * 32;
#pragma unroll
        for (int i = 0; i < 2; i++) {
            int e = tid + i * 256;
            int row = e >> 2, ch = e & 3;
            cpa16(as + row * STR + ch * 16, Ab + (size_t)row * 768 + k0 + ch * 8);
            cpa16(bs + row * STR + ch * 16, Bb + (size_t)row * 768 + k0 + ch * 8);
        }
        asm volatile("cp.async.commit_group;" ::: "memory");
    };

    float acc[4][4][4];
#pragma unroll
    for (int i = 0; i < 4; i++)
#pragma unroll
        for (int j = 0; j < 4; j++)
#pragma unroll
            for (int r = 0; r < 4; r++) acc[i][j][r] = 0.f;

    load(0);
    load(1);
    for (int kt = 0; kt < nk; kt++) {
        asm volatile("cp.async.wait_group 1;" ::: "memory");
        __syncthreads();
        int st = kt % 3;
        uint32_t as = smb + st * SSTAGE + (wm * 64 + (lane & 15)) * STR + (lane >> 4) * 16;
        uint32_t bs = smb + 3 * SSTAGE + st * SSTAGE + (wn * 32 + (lane & 15)) * STR + (lane >> 4) * 16;
#pragma unroll
        for (int kk = 0; kk < 2; kk++) {
            uint32_t a[4][4], bb[2][4];
#pragma unroll
            for (int mt = 0; mt < 4; mt++) ldm4(a[mt], as + mt * 16 * STR + kk * 32);
#pragma unroll
            for (int nt = 0; nt < 2; nt++) ldm4(bb[nt], bs + nt * 16 * STR + kk * 32);
#pragma unroll
            for (int mt = 0; mt < 4; mt++)
#pragma unroll
                for (int n8 = 0; n8 < 4; n8++)
                    mma16(acc[mt][n8], a[mt], bb[n8 >> 1][n8 & 1], bb[n8 >> 1][(n8 & 1) + 2]);
        }
        __syncthreads();
        if (kt + 2 < nk) load(kt + 2);
        else asm volatile("cp.async.commit_group;" ::: "memory");
    }

    // write S tile
    float* Cb = C + (size_t)bz * 4096 * 4096;
#pragma unroll
    for (int mt = 0; mt < 4; mt++) {
        int row = m0 + wm * 64 + mt * 16 + (lane >> 2);
#pragma unroll
        for (int n8 = 0; n8 < 4; n8++) {
            int col = n0 + wn * 32 + n8 * 8 + (lane & 3) * 2;
            float2 v0, v1;
            v0.x = acc[mt][n8][0]; v0.y = acc[mt][n8][1];
            v1.x = acc[mt][n8][2]; v1.y = acc[mt][n8][3];
            *(float2*)&Cb[(size_t)row * 4096 + col] = v0;
            *(float2*)&Cb[(size_t)(row + 8) * 4096 + col] = v1;
        }
    }

    // fused partial softmax stats over this CTA's 128-k slice
    float lm[8], ls[8];
#pragma unroll
    for (int mt = 0; mt < 4; mt++) {
#pragma unroll
        for (int h = 0; h < 2; h++) {
            float m = -3.4e38f;
#pragma unroll
            for (int n8 = 0; n8 < 4; n8++)
                m = fmaxf(m, fmaxf(acc[mt][n8][2 * h], acc[mt][n8][2 * h + 1]));
            m = fmaxf(m, __shfl_xor_sync(0xFFFFFFFF, m, 1));
            m = fmaxf(m, __shfl_xor_sync(0xFFFFFFFF, m, 2));
            float s = 0.f;
#pragma unroll
            for (int n8 = 0; n8 < 4; n8++)
                s += fexp(acc[mt][n8][2 * h] - m) + fexp(acc[mt][n8][2 * h + 1] - m);
            s += __shfl_xor_sync(0xFFFFFFFF, s, 1);
            s += __shfl_xor_sync(0xFFFFFFFF, s, 2);
            lm[mt * 2 + h] = m;
            ls[mt * 2 + h] = s;
        }
    }
    __syncthreads();      // stage smem dead, reuse for stats
    float* sm_m = (float*)sm_;           // [128][4]
    float* sm_s = (float*)(sm_ + 2048);  // [128][4]
    if ((lane & 3) == 0) {
#pragma unroll
        for (int mt = 0; mt < 4; mt++)
#pragma unroll
            for (int h = 0; h < 2; h++) {
                int r = wm * 64 + mt * 16 + h * 8 + (lane >> 2);
                sm_m[r * 4 + wn] = lm[mt * 2 + h];
                sm_s[r * 4 + wn] = ls[mt * 2 + h];
            }
    }
    __syncthreads();
    if (tid < 128) {
        float m0v = sm_m[tid * 4 + 0], m1 = sm_m[tid * 4 + 1];
        float m2 = sm_m[tid * 4 + 2], m3 = sm_m[tid * 4 + 3];
        float mg = fmaxf(fmaxf(m0v, m1), fmaxf(m2, m3));
        float Z = fexp(m0v - mg) * sm_s[tid * 4 + 0] + fexp(m1 - mg) * sm_s[tid * 4 + 1]
                + fexp(m2 - mg) * sm_s[tid * 4 + 2] + fexp(m3 - mg) * sm_s[tid * 4 + 3];
        size_t o = ((size_t)bz * 32 + blockIdx.x) * 4096 + m0 + tid;
        g_pm[o] = mg;
        g_ps[o] = Z;
    }
}

// combine 32 tile partials + border key -> m, 1/Z, bw
__global__ void sm_combine() {
    int i = blockIdx.x * 256 + threadIdx.x;    // b*4096+q
    int b = i >> 12, q = i & 4095;
    float sbv = g_sb[i];
    float mg = sbv;
#pragma unroll 8
    for (int t = 0; t < 32; t++)
        mg = fmaxf(mg, g_pm[((size_t)b * 32 + t) * 4096 + q]);
    float Z = 260.f * fexp(sbv - mg);
    float eb = Z;
#pragma unroll 8
    for (int t = 0; t < 32; t++) {
        size_t o = ((size_t)b * 32 + t) * 4096 + q;
        Z += fexp(g_pm[o] - mg) * g_ps[o];
    }
    float iz = 1.f / Z;
    g_m[i] = mg;
    g_iz[i] = iz;
    g_bw[i] = eb * iz;
}

// ---------------------------------------------------------------------------
// Fused O GEMM: out[c][q] = sum_k V[c][k] * exp(S[q][k]-m[q])*iz[q]  (+bw[q]*vbv[c])
// ---------------------------------------------------------------------------
#define OASTG (2*256*STR)
#define OB0   (3*OASTG)
#define OBSTG (2*128*STR)
#define GSMEM_O (OB0 + 2*OBSTG)

__global__ __launch_bounds__(256, 1) void gemm_o(float* __restrict__ Cout)
{
    extern __shared__ char sm_[];
    uint32_t smb = smem_u32(sm_);
    int tid = threadIdx.x, lane = tid & 31, wid = tid >> 5;
    int wm = wid >> 1, wn = wid & 1;
    int b = blockIdx.z;
    int n0 = blockIdx.x * 128;
    const __nv_bfloat16* Vb = g_vh2 + (size_t)b * 2 * NC * NPIX;
    const int nk = 128;

    int brow = tid >> 1, half = tid & 1;
    int q = n0 + brow;
    float mq = g_m[b * 4096 + q];
    float izq = g_iz[b * 4096 + q];
    const float* Sg = g_S + ((size_t)b * 4096 + q) * 4096 + half * 16;

    auto loadA = [&](int kt) {
        int st = kt % 3;
#pragma unroll
        for (int u = 0; u < 8; u++) {
            int e = tid + u * 256;
            int ts = e >> 10;
            int e2 = e & 1023;
            int row = e2 >> 2, ch = e2 & 3;
            cpa16(smb + st * OASTG + ts * (256 * STR) + row * STR + ch * 16,
                  Vb + ((size_t)ts * NC + row) * 4096 + kt * 32 + ch * 8);
        }
        asm volatile("cp.async.commit_group;" ::: "memory");
    };

    float acc[4][8][4];
#pragma unroll
    for (int i = 0; i < 4; i++)
#pragma unroll
        for (int j = 0; j < 8; j++)
#pragma unroll
            for (int r = 0; r < 4; r++) acc[i][j][r] = 0.f;

    float4 f[4];
    loadA(0);
    loadA(1);
#pragma unroll
    for (int i = 0; i < 4; i++) f[i] = ((const float4*)Sg)[i];

    for (int kt = 0; kt < nk; kt++) {
        asm volatile("cp.async.wait_group 1;" ::: "memory");
        __syncthreads();
        {
            float e16[16];
            float* fp = (float*)f;
#pragma unroll
            for (int j = 0; j < 16; j++) e16[j] = fexp(fp[j] - mq) * izq;
            __nv_bfloat16 hh[16], ll[16];
#pragma unroll
            for (int j = 0; j < 16; j++) split2(e16[j], hh[j], ll[j]);
            int b2 = kt & 1;
            char* bp = sm_ + OB0 + b2 * OBSTG + brow * STR + half * 32;
            *(uint4*)bp = ((uint4*)hh)[0];
            *(uint4*)(bp + 16) = ((uint4*)hh)[1];
            *(uint4*)(bp + 128 * STR) = ((uint4*)ll)[0];
            *(uint4*)(bp + 128 * STR + 16) = ((uint4*)ll)[1];
        }
        if (kt + 1 < nk) {
            const float4* s4 = (const float4*)(Sg + (kt + 1) * 32);
#pragma unroll
            for (int i = 0; i < 4; i++) f[i] = s4[i];
        }
        if (kt + 2 < nk) loadA(kt + 2);
        else asm volatile("cp.async.commit_group;" ::: "memory");
        __syncthreads();

        int st = kt % 3, b2 = kt & 1;
        uint32_t ash = smb + st * OASTG + (wm * 64 + (lane & 15)) * STR + (lane >> 4) * 16;
        uint32_t asl = ash + 256 * STR;
        uint32_t bsp = smb + OB0 + b2 * OBSTG + (wn * 64 + (lane & 15)) * STR + (lane >> 4) * 16;
        uint32_t bsl = bsp + 128 * STR;
#pragma unroll
        for (int kk = 0; kk < 2; kk++) {
            uint32_t ah[4][4], al[4][4], bh[4][4], bl[4][4];
#pragma unroll
            for (int mt = 0; mt < 4; mt++) ldm4(ah[mt], ash + mt * 16 * STR + kk * 32);
#pragma unroll
            for (int nt = 0; nt < 4; nt++) ldm4(bh[nt], bsp + nt * 16 * STR + kk * 32);
#pragma unroll
            for (int mt = 0; mt < 4; mt++)
#pragma unroll
                for (int n8 = 0; n8 < 8; n8++)
                    mma16(acc[mt][n8], ah[mt], bh[n8 >> 1][n8 & 1], bh[n8 >> 1][(n8 & 1) + 2]);
#pragma unroll
            for (int nt = 0; nt < 4; nt++) ldm4(bl[nt], bsl + nt * 16 * STR + kk * 32);
#pragma unroll
            for (int mt = 0; mt < 4; mt++)
#pragma unroll
                for (int n8 = 0; n8 < 8; n8++)
                    mma16(acc[mt][n8], ah[mt], bl[n8 >> 1][n8 & 1], bl[n8 >> 1][(n8 & 1) + 2]);
#pragma unroll
            for (int mt = 0; mt < 4; mt++) ldm4(al[mt], asl + mt * 16 * STR + kk * 32);
#pragma unroll
            for (int mt = 0; mt < 4; mt++)
#pragma unroll
                for (int n8 = 0; n8 < 8; n8++)
                    mma16(acc[mt][n8], al[mt], bh[n8 >> 1][n8 & 1], bh[n8 >> 1][(n8 & 1) + 2]);
        }
    }

    float* Cb = Cout + (size_t)b * NC * NPIX;
    const float* bwp = g_bw + (size_t)b * 4096;
#pragma unroll
    for (int mt = 0; mt < 4; mt++) {
        int row = wm * 64 + mt * 16 + (lane >> 2);
        float vb0 = g_vbv[row], vb1 = g_vbv[row + 8];
#pragma unroll
        for (int n8 = 0; n8 < 8; n8++) {
            int col = n0 + wn * 64 + n8 * 8 + (lane & 3) * 2;
            float w0 = bwp[col], w1 = bwp[col + 1];
            float2 v0, v1;
            v0.x = fmaf(w0, vb0, acc[mt][n8][0]); v0.y = fmaf(w1, vb0, acc[mt][n8][1]);
            v1.x = fmaf(w0, vb1, acc[mt][n8][2]); v1.y = fmaf(w1, vb1, acc[mt][n8][3]);
            *(float2*)&Cb[(size_t)row * 4096 + col] = v0;
            *(float2*)&Cb[(size_t)(row + 8) * 4096 + col] = v1;
        }
    }
}

// ---- prep kernels ----
__global__ void zero_k(uint4* p, int n) {
    int i = blockIdx.x * 256 + threadIdx.x;
    if (i < n) p[i] = make_uint4(0, 0, 0, 0);
}

__global__ void xt_fill(const float* __restrict__ x) {
    __shared__ float tile[32][33];
    int b = blockIdx.z;
    int p0 = blockIdx.x * 32, c0 = blockIdx.y * 32;
    int tx = threadIdx.x, ty = threadIdx.y;
    const float* s = x + (size_t)b * NC * NPIX;
    for (int j = 0; j < 32; j += 8)
        tile[ty + j][tx] = s[(size_t)(c0 + ty + j) * NPIX + p0 + tx];
    __syncthreads();
    for (int j = 0; j < 32; j += 8) {
        int p = p0 + ty + j, y = p >> 6, xx = p & 63;
        size_t o = ((size_t)b * 4356 + (y + 1) * 66 + (xx + 1)) * 256 + c0 + tx;
        __nv_bfloat16 h, l;
        split2(tile[tx][ty + j], h, l);
        g_xt_h[o] = h;
        g_xt_l[o] = l;
    }
}

__global__ void wsplit_q(const float* __restrict__ w) {
    int idx = blockIdx.x * 256 + threadIdx.x;
    if (idx >= NC * 2304) return;
    int m = idx / 2304, r = idx % 2304;
    int c = r / 9, t = r % 9;
    __nv_bfloat16 h, l;
    split2(w[idx], h, l);
    size_t base = (size_t)m * 6912 + t * 256 + c;
    g_wqh[base] = h; g_wqh[base + 2304] = h; g_wqh[base + 4608] = l;
}

__global__ void wsplit1(const float* __restrict__ w, __nv_bfloat16* __restrict__ o) {
    int idx = blockIdx.x * 256 + threadIdx.x;
    if (idx >= NC * NC) return;
    int m = idx / NC, c = idx % NC;
    __nv_bfloat16 h, l;
    split2(w[idx], h, l);
    size_t base = (size_t)m * 768 + c;
    o[base] = h; o[base + 256] = h; o[base + 512] = l;
}

__global__ void tsplit(const float* __restrict__ src, __nv_bfloat16* __restrict__ dst,
                       const float* __restrict__ aa, const float* __restrict__ ad, int patA) {
    __shared__ float tile[32][33];
    int b = blockIdx.z;
    int p0 = blockIdx.x * 32, c0 = blockIdx.y * 32;
    int tx = threadIdx.x, ty = threadIdx.y;
    const float* s = src + (size_t)b * NC * NPIX;
    for (int j = 0; j < 32; j += 8) {
        float a = aa[c0 + ty + j], d = ad[c0 + ty + j];
        tile[ty + j][tx] = fmaf(a, s[(size_t)(c0 + ty + j) * NPIX + p0 + tx], d);
    }
    __syncthreads();
    for (int j = 0; j < 32; j += 8) {
        __nv_bfloat16 h, l;
        split2(tile[tx][ty + j], h, l);
        __nv_bfloat16* o = dst + ((size_t)b * 4096 + p0 + ty + j) * 768 + c0 + tx;
        o[0] = h;
        o[256] = patA ? h : l;
        o[512] = patA ? l : h;
    }
}

__global__ void vhl_k() {
    size_t i4 = (size_t)blockIdx.x * 256 + threadIdx.x;
    size_t e = i4 * 4;
    int c = (int)((e >> 12) & 255);
    int b = (int)(e >> 20);
    int k = (int)(e & 4095);
    float a = g_a[512 + c], d = g_dd[512 + c];
    float4 v = *(float4*)(g_vc + e);
    __nv_bfloat16 h[4], l[4];
    split2(fmaf(a, v.x, d), h[0], l[0]);
    split2(fmaf(a, v.y, d), h[1], l[1]);
    split2(fmaf(a, v.z, d), h[2], l[2]);
    split2(fmaf(a, v.w, d), h[3], l[3]);
    *(uint2*)(g_vh2 + ((size_t)(b * 2 + 0) * 256 + c) * 4096 + k) = *(uint2*)h;
    *(uint2*)(g_vh2 + ((size_t)(b * 2 + 1) * 256 + c) * 4096 + k) = *(uint2*)l;
}

__global__ void stats_k(const float* __restrict__ bq, const float* __restrict__ gq, const float* __restrict__ betaq,
                        const float* __restrict__ bk, const float* __restrict__ gk, const float* __restrict__ betak,
                        const float* __restrict__ bv, const float* __restrict__ gv, const float* __restrict__ betav)
{
    int c = blockIdx.x, t = blockIdx.y;
    const float* src = (t == 0) ? g_qc : (t == 1) ? g_kc : g_vc;
    int tid = threadIdx.x;
    float s1 = 0.f, s2 = 0.f;
    for (int b = 0; b < NB; b++) {
        const float* p = src + ((size_t)b * NC + c) * NPIX;
        for (int i = tid; i < NPIX; i += 256) {
            float v = p[i];
            s1 += v; s2 += v * v;
        }
    }
    __shared__ double r1[256], r2[256];
    r1[tid] = s1; r2[tid] = s2;
    __syncthreads();
    for (int s = 128; s > 0; s >>= 1) {
        if (tid < s) { r1[tid] += r1[tid + s]; r2[tid] += r2[tid + s]; }
        __syncthreads();
    }
    if (tid == 0) {
        double S1 = r1[0], S2 = r2[0], cnt = 16384.0;
        float bias = (t == 0) ? bq[c] : (t == 1) ? bk[c] : bv[c];
        float g    = (t == 0) ? gq[c] : (t == 1) ? gk[c] : gv[c];
        float be   = (t == 0) ? betaq[c] : (t == 1) ? betak[c] : betav[c];
        if (t > 0) {
            cnt = 17424.0;
            S1 += 1040.0 * (double)bias;
            S2 += 1040.0 * (double)bias * (double)bias;
        }
        double mean = S1 / cnt;
        double var = S2 / cnt - mean * mean;
        float a = g * rsqrtf((float)var + 1e-5f);
        float d = be - a * (float)mean;
        g_a[t * NC + c] = a;
        g_dd[t * NC + c] = d;
        if (t == 1) g_kbv[c] = fmaf(a, bias, d);
        if (t == 2) g_vbv[c] = fmaf(a, bias, d);
    }
}

__global__ void sb_k() {
    int b = blockIdx.y;
    int q = blockIdx.x * 256 + threadIdx.x;
    const float* Q = g_qc + (size_t)b * NC * NPIX;
    float s = 0.f;
#pragma unroll 8
    for (int c = 0; c < NC; c++) {
        float qn = fmaf(g_a[c], Q[(size_t)c * NPIX + q], g_dd[c]);
        s = fmaf(g_kbv[c], qn, s);
    }
    g_sb[b * NPIX + q] = s;
}

// ---------------------------------------------------------------------------
extern "C" void kernel_launch(void* const* d_in, const int* in_sizes, int n_in,
                              void* d_out, int out_size)
{
    const float* x     = (const float*)d_in[0];
    const float* Wq    = (const float*)d_in[1];
    const float* bq    = (const float*)d_in[2];
    const float* gq    = (const float*)d_in[3];
    const float* betaq = (const float*)d_in[4];
    const float* Wk    = (const float*)d_in[5];
    const float* bk    = (const float*)d_in[6];
    const float* gk    = (const float*)d_in[7];
    const float* betak = (const float*)d_in[8];
    const float* Wv    = (const float*)d_in[9];
    const float* bv    = (const float*)d_in[10];
    const float* gv    = (const float*)d_in[11];
    const float* betav = (const float*)d_in[12];
    float* out = (float*)d_out;

    cudaFuncSetAttribute(gemm_conv<9>, cudaFuncAttributeMaxDynamicSharedMemorySize, GSMEM_C);
    cudaFuncSetAttribute(gemm_conv<1>, cudaFuncAttributeMaxDynamicSharedMemorySize, GSMEM_C);
    cudaFuncSetAttribute(gemm_s, cudaFuncAttributeMaxDynamicSharedMemorySize, GSMEM_S);
    cudaFuncSetAttribute(gemm_o, cudaFuncAttributeMaxDynamicSharedMemorySize, GSMEM_O);

    __nv_bfloat16 *p_xth, *p_xtl, *p_wqh, *p_wkh, *p_wvh, *p_qth, *p_kth;
    float *p_qc, *p_kc, *p_vc, *p_S, *p_a, *p_dd;
    cudaGetSymbolAddress((void**)&p_xth, g_xt_h);
    cudaGetSymbolAddress((void**)&p_xtl, g_xt_l);
    cudaGetSymbolAddress((void**)&p_wqh, g_wqh);
    cudaGetSymbolAddress((void**)&p_wkh, g_wkh);
    cudaGetSymbolAddress((void**)&p_wvh, g_wvh);
    cudaGetSymbolAddress((void**)&p_qth, g_qth);
    cudaGetSymbolAddress((void**)&p_kth, g_kth);
    cudaGetSymbolAddress((void**)&p_qc,  g_qc);
    cudaGetSymbolAddress((void**)&p_kc,  g_kc);
    cudaGetSymbolAddress((void**)&p_vc,  g_vc);
    cudaGetSymbolAddress((void**)&p_S,   g_S);
    cudaGetSymbolAddress((void**)&p_a,   g_a);
    cudaGetSymbolAddress((void**)&p_dd,  g_dd);

    // 1. padded transposed hi/lo x + weight splits
    int nz = (int)(((size_t)NB * 4356 * 256 * 2 / 16 + 255) / 256);
    zero_k<<<nz, 256>>>((uint4*)p_xth, (int)((size_t)NB * 4356 * 256 * 2 / 16));
    zero_k<<<nz, 256>>>((uint4*)p_xtl, (int)((size_t)NB * 4356 * 256 * 2 / 16));
    xt_fill<<<dim3(128, 8, NB), dim3(32, 8)>>>(x);
    wsplit_q<<<(NC * 2304 + 255) / 256, 256>>>(Wq);
    wsplit1<<<(NC * NC + 255) / 256, 256>>>(Wk, p_wkh);
    wsplit1<<<(NC * NC + 255) / 256, 256>>>(Wv, p_wvh);

    // 2. convs (implicit im2col, BM=128, occ 2)
    gemm_conv<9><<<dim3(32, 2, NB), 256, GSMEM_C>>>(p_wqh, p_qc, bq);
    gemm_conv<1><<<dim3(32, 2, NB), 256, GSMEM_C>>>(p_wkh, p_kc, bk);
    gemm_conv<1><<<dim3(32, 2, NB), 256, GSMEM_C>>>(p_wvh, p_vc, bv);

    // 3. BN stats + splits + border scores
    stats_k<<<dim3(256, 3), 256>>>(bq, gq, betaq, bk, gk, betak, bv, gv, betav);
    tsplit<<<dim3(128, 8, NB), dim3(32, 8)>>>(p_qc, p_qth, p_a, p_dd, 1);
    tsplit<<<dim3(128, 8, NB), dim3(32, 8)>>>(p_kc, p_kth, p_a + 256, p_dd + 256, 0);
    vhl_k<<<(int)(((size_t)NB * NC * NPIX / 4) / 256), 256>>>();
    sb_k<<<dim3(16, NB), 256>>>();

    // 4. S[q][k] + fused partial softmax stats
    gemm_s<<<dim3(32, 32, NB), 256, GSMEM_S>>>(p_qth, p_kth, p_S);

    // 5. combine partials -> m, 1/Z, bw
    sm_combine<<<64, 256>>>();

    // 6. fused O GEMM (exp/split in-kernel)
    gemm_o<<<dim3(32, 1, NB), 256, GSMEM_O>>>(out);
}

// round 8
// speedup vs baseline: 2.2715x; 1.2365x over previous
#include <cuda_runtime.h>
#include <cuda_bf16.h>
#include <cuda_fp16.h>
#include <math.h>
#include <stdint.h>

#define NB 4
#define NC 256
#define NPIX 4096
#define STR 80

// ---- static device scratch ----
__device__ __nv_bfloat16 g_xt_h[(size_t)NB*4356*256];   // padded x, [b][pix66][c] hi
__device__ __nv_bfloat16 g_xt_l[(size_t)NB*4356*256];   // lo
__device__ __nv_bfloat16 g_wqh[NC*6912];                // Wq split, A-pat [h,h,l], k=t*256+c
__device__ __nv_bfloat16 g_wkh[NC*768];
__device__ __nv_bfloat16 g_wvh[NC*768];
__device__ float g_qc[(size_t)NB*NC*NPIX];
__device__ float g_kc[(size_t)NB*NC*NPIX];
__device__ float g_vc[(size_t)NB*NC*NPIX];
__device__ __nv_bfloat16 g_qth[(size_t)NB*NPIX*768];    // BN(Q)^T, A-pat
__device__ __nv_bfloat16 g_kth[(size_t)NB*NPIX*768];    // BN(K)^T, B-pat
__device__ __half g_vf[(size_t)NB*NC*NPIX];             // BN(V) fp16 [b][c][k]
__device__ float g_S[(size_t)NB*NPIX*NPIX];             // scores [b][q][k]
__device__ float g_pm[(size_t)NB*32*NPIX];              // per-tile max  [b][t][q]
__device__ float g_ps[(size_t)NB*32*NPIX];              // per-tile sum  [b][t][q]
__device__ float g_sb[NB*NPIX];
__device__ float g_bw[NB*NPIX];
__device__ float g_m[NB*NPIX];
__device__ float g_iz[NB*NPIX];
__device__ float g_a[3*NC];
__device__ float g_dd[3*NC];
__device__ float g_kbv[NC];
__device__ float g_vbv[NC];

// ---- helpers ----
__device__ __forceinline__ uint32_t smem_u32(const void* p) {
    uint32_t a;
    asm("{ .reg .u64 t; cvta.to.shared.u64 t, %1; cvt.u32.u64 %0, t; }" : "=r"(a) : "l"(p));
    return a;
}
__device__ __forceinline__ void cpa16(uint32_t s, const void* g) {
    asm volatile("cp.async.cg.shared.global [%0], [%1], 16;" :: "r"(s), "l"(g));
}
__device__ __forceinline__ void ldm4(uint32_t* r, uint32_t addr) {
    asm volatile("ldmatrix.sync.aligned.m8n8.x4.shared.b16 {%0,%1,%2,%3}, [%4];"
                 : "=r"(r[0]), "=r"(r[1]), "=r"(r[2]), "=r"(r[3]) : "r"(addr));
}
__device__ __forceinline__ void mma16(float* d, const uint32_t* a, uint32_t b0, uint32_t b1) {
    asm volatile(
        "mma.sync.aligned.m16n8k16.row.col.f32.bf16.bf16.f32 "
        "{%0,%1,%2,%3}, {%4,%5,%6,%7}, {%8,%9}, {%0,%1,%2,%3};"
        : "+f"(d[0]), "+f"(d[1]), "+f"(d[2]), "+f"(d[3])
        : "r"(a[0]), "r"(a[1]), "r"(a[2]), "r"(a[3]), "r"(b0), "r"(b1));
}
__device__ __forceinline__ void mma16h(float* d, const uint32_t* a, uint32_t b0, uint32_t b1) {
    asm volatile(
        "mma.sync.aligned.m16n8k16.row.col.f32.f16.f16.f32 "
        "{%0,%1,%2,%3}, {%4,%5,%6,%7}, {%8,%9}, {%0,%1,%2,%3};"
        : "+f"(d[0]), "+f"(d[1]), "+f"(d[2]), "+f"(d[3])
        : "r"(a[0]), "r"(a[1]), "r"(a[2]), "r"(a[3]), "r"(b0), "r"(b1));
}
__device__ __forceinline__ float fexp(float x) {
    x = fmaxf(x, -87.0f);
    float t = fmaf(x, 1.4426950408889634f, 12582912.0f);
    float i = t - 12582912.0f;
    float f = fmaf(x, 1.4426950408889634f, -i);
    float y = f * 0.6931471805599453f;
    float p = fmaf(y, 0.0083333338f, 0.041666668f);
    p = fmaf(y, p, 0.16666667f);
    p = fmaf(y, p, 0.5f);
    p = fmaf(y, p, 1.0f);
    p = fmaf(y, p, 1.0f);
    return p * __int_as_float(((int)i + 127) << 23);
}
__device__ __forceinline__ void split2(float v, __nv_bfloat16& h, __nv_bfloat16& l) {
    h = __float2bfloat16(v);
    l = __float2bfloat16(v - __bfloat162float(h));
}

// ---------------------------------------------------------------------------
// Implicit-im2col conv GEMM (bf16x3): BM=128, BN=128, BK=32, occ 2.
// ---------------------------------------------------------------------------
#define CSTAGE (2*128*STR)
#define GSMEM_C (3*CSTAGE)

template <int TAPS>
__global__ __launch_bounds__(256, 2) void gemm_conv(
    const __nv_bfloat16* __restrict__ W, float* __restrict__ C,
    const float* __restrict__ bias)
{
    extern __shared__ char sm_[];
    uint32_t smb = smem_u32(sm_);
    int tid = threadIdx.x, lane = tid & 31, wid = tid >> 5;
    int wm = wid & 1, wn = wid >> 1;
    int b = blockIdx.z;
    int m0 = blockIdx.y * 128, n0 = blockIdx.x * 128;
    const int Kp = TAPS * 768;
    const int nk = TAPS * 24;
    const __nv_bfloat16* XH = g_xt_h + (size_t)b * 4356 * 256;
    const __nv_bfloat16* XL = g_xt_l + (size_t)b * 4356 * 256;
    const __nv_bfloat16* Wb = W + (size_t)m0 * Kp;

    auto load = [&](int kt) {
        int st = kt % 3;
        uint32_t as = smb + st * CSTAGE;
        uint32_t bs = smb + st * CSTAGE + 128 * STR;
        int blk = kt / (TAPS * 8);
        int rem = kt - blk * (TAPS * 8);
        int t = rem >> 3, c0 = (rem & 7) << 5;
        int dy = (TAPS == 9) ? t / 3 : 1;
        int dx = (TAPS == 9) ? t % 3 : 1;
        const __nv_bfloat16* buf = (blk == 1) ? XL : XH;
#pragma unroll
        for (int u = 0; u < 2; u++) {
            int e = tid + u * 256;
            int row = e >> 2, ch = e & 3;
            cpa16(as + row * STR + ch * 16, Wb + (size_t)row * Kp + kt * 32 + ch * 8);
        }
#pragma unroll
        for (int u = 0; u < 2; u++) {
            int e = tid + u * 256;
            int row = e >> 2, ch = e & 3;
            int p = n0 + row, y = p >> 6, xx = p & 63;
            cpa16(bs + row * STR + ch * 16,
                  buf + (size_t)((y + dy) * 66 + (xx + dx)) * 256 + c0 + ch * 8);
        }
        asm volatile("cp.async.commit_group;" ::: "memory");
    };

    float acc[4][4][4];
#pragma unroll
    for (int i = 0; i < 4; i++)
#pragma unroll
        for (int j = 0; j < 4; j++)
#pragma unroll
            for (int r = 0; r < 4; r++) acc[i][j][r] = 0.f;

    load(0);
    load(1);
    for (int kt = 0; kt < nk; kt++) {
        asm volatile("cp.async.wait_group 1;" ::: "memory");
        __syncthreads();
        int st = kt % 3;
        uint32_t as = smb + st * CSTAGE + (wm * 64 + (lane & 15)) * STR + (lane >> 4) * 16;
        uint32_t bs = smb + st * CSTAGE + 128 * STR + (wn * 32 + (lane & 15)) * STR + (lane >> 4) * 16;
#pragma unroll
        for (int kk = 0; kk < 2; kk++) {
            uint32_t a[4][4], bb[2][4];
#pragma unroll
            for (int mt = 0; mt < 4; mt++) ldm4(a[mt], as + mt * 16 * STR + kk * 32);
#pragma unroll
            for (int nt = 0; nt < 2; nt++) ldm4(bb[nt], bs + nt * 16 * STR + kk * 32);
#pragma unroll
            for (int mt = 0; mt < 4; mt++)
#pragma unroll
                for (int n8 = 0; n8 < 4; n8++)
                    mma16(acc[mt][n8], a[mt], bb[n8 >> 1][n8 & 1], bb[n8 >> 1][(n8 & 1) + 2]);
        }
        __syncthreads();
        if (kt + 2 < nk) load(kt + 2);
        else asm volatile("cp.async.commit_group;" ::: "memory");
    }

    float* Cb = C + (size_t)b * NC * NPIX;
#pragma unroll
    for (int mt = 0; mt < 4; mt++) {
        int row = m0 + wm * 64 + mt * 16 + (lane >> 2);
        float bi0 = bias[row], bi1 = bias[row + 8];
#pragma unroll
        for (int n8 = 0; n8 < 4; n8++) {
            int col = n0 + wn * 32 + n8 * 8 + (lane & 3) * 2;
            float2 v0, v1;
            v0.x = acc[mt][n8][0] + bi0; v0.y = acc[mt][n8][1] + bi0;
            v1.x = acc[mt][n8][2] + bi1; v1.y = acc[mt][n8][3] + bi1;
            *(float2*)&Cb[(size_t)row * 4096 + col] = v0;
            *(float2*)&Cb[(size_t)(row + 8) * 4096 + col] = v1;
        }
    }
}

// ---------------------------------------------------------------------------
// S GEMM (bf16x3) + fused partial softmax stats.
// ---------------------------------------------------------------------------
#define SSTAGE (128*STR)
#define GSMEM_S (6*SSTAGE)

__global__ __launch_bounds__(256, 2) void gemm_s(
    const __nv_bfloat16* __restrict__ A, const __nv_bfloat16* __restrict__ B,
    float* __restrict__ C)
{
    extern __shared__ char sm_[];
    uint32_t smb = smem_u32(sm_);
    int tid = threadIdx.x, lane = tid & 31, wid = tid >> 5;
    int wm = wid & 1, wn = wid >> 1;
    int bz = blockIdx.z;
    int m0 = blockIdx.y * 128, n0 = blockIdx.x * 128;
    const __nv_bfloat16* Ab = A + (size_t)bz * 4096 * 768 + (size_t)m0 * 768;
    const __nv_bfloat16* Bb = B + (size_t)bz * 4096 * 768 + (size_t)n0 * 768;
    const int nk = 24;

    auto load = [&](int kt) {
        int st = kt % 3;
        uint32_t as = smb + st * SSTAGE;
        uint32_t bs = smb + 3 * SSTAGE + st * SSTAGE;
        int k0 = kt * 32;
#pragma unroll
        for (int i = 0; i < 2; i++) {
            int e = tid + i * 256;
            int row = e >> 2, ch = e & 3;
            cpa16(as + row * STR + ch * 16, Ab + (size_t)row * 768 + k0 + ch * 8);
            cpa16(bs + row * STR + ch * 16, Bb + (size_t)row * 768 + k0 + ch * 8);
        }
        asm volatile("cp.async.commit_group;" ::: "memory");
    };

    float acc[4][4][4];
#pragma unroll
    for (int i = 0; i < 4; i++)
#pragma unroll
        for (int j = 0; j < 4; j++)
#pragma unroll
            for (int r = 0; r < 4; r++) acc[i][j][r] = 0.f;

    load(0);
    load(1);
    for (int kt = 0; kt < nk; kt++) {
        asm volatile("cp.async.wait_group 1;" ::: "memory");
        __syncthreads();
        int st = kt % 3;
        uint32_t as = smb + st * SSTAGE + (wm * 64 + (lane & 15)) * STR + (lane >> 4) * 16;
        uint32_t bs = smb + 3 * SSTAGE + st * SSTAGE + (wn * 32 + (lane & 15)) * STR + (lane >> 4) * 16;
#pragma unroll
        for (int kk = 0; kk < 2; kk++) {
            uint32_t a[4][4], bb[2][4];
#pragma unroll
            for (int mt = 0; mt < 4; mt++) ldm4(a[mt], as + mt * 16 * STR + kk * 32);
#pragma unroll
            for (int nt = 0; nt < 2; nt++) ldm4(bb[nt], bs + nt * 16 * STR + kk * 32);
#pragma unroll
            for (int mt = 0; mt < 4; mt++)
#pragma unroll
                for (int n8 = 0; n8 < 4; n8++)
                    mma16(acc[mt][n8], a[mt], bb[n8 >> 1][n8 & 1], bb[n8 >> 1][(n8 & 1) + 2]);
        }
        __syncthreads();
        if (kt + 2 < nk) load(kt + 2);
        else asm volatile("cp.async.commit_group;" ::: "memory");
    }

    float* Cb = C + (size_t)bz * 4096 * 4096;
#pragma unroll
    for (int mt = 0; mt < 4; mt++) {
        int row = m0 + wm * 64 + mt * 16 + (lane >> 2);
#pragma unroll
        for (int n8 = 0; n8 < 4; n8++) {
            int col = n0 + wn * 32 + n8 * 8 + (lane & 3) * 2;
            float2 v0, v1;
            v0.x = acc[mt][n8][0]; v0.y = acc[mt][n8][1];
            v1.x = acc[mt][n8][2]; v1.y = acc[mt][n8][3];
            *(float2*)&Cb[(size_t)row * 4096 + col] = v0;
            *(float2*)&Cb[(size_t)(row + 8) * 4096 + col] = v1;
        }
    }

    float lm[8], ls[8];
#pragma unroll
    for (int mt = 0; mt < 4; mt++) {
#pragma unroll
        for (int h = 0; h < 2; h++) {
            float m = -3.4e38f;
#pragma unroll
            for (int n8 = 0; n8 < 4; n8++)
                m = fmaxf(m, fmaxf(acc[mt][n8][2 * h], acc[mt][n8][2 * h + 1]));
            m = fmaxf(m, __shfl_xor_sync(0xFFFFFFFF, m, 1));
            m = fmaxf(m, __shfl_xor_sync(0xFFFFFFFF, m, 2));
            float s = 0.f;
#pragma unroll
            for (int n8 = 0; n8 < 4; n8++)
                s += fexp(acc[mt][n8][2 * h] - m) + fexp(acc[mt][n8][2 * h + 1] - m);
            s += __shfl_xor_sync(0xFFFFFFFF, s, 1);
            s += __shfl_xor_sync(0xFFFFFFFF, s, 2);
            lm[mt * 2 + h] = m;
            ls[mt * 2 + h] = s;
        }
    }
    __syncthreads();
    float* sm_m = (float*)sm_;
    float* sm_s = (float*)(sm_ + 2048);
    if ((lane & 3) == 0) {
#pragma unroll
        for (int mt = 0; mt < 4; mt++)
#pragma unroll
            for (int h = 0; h < 2; h++) {
                int r = wm * 64 + mt * 16 + h * 8 + (lane >> 2);
                sm_m[r * 4 + wn] = lm[mt * 2 + h];
                sm_s[r * 4 + wn] = ls[mt * 2 + h];
            }
    }
    __syncthreads();
    if (tid < 128) {
        float m0v = sm_m[tid * 4 + 0], m1 = sm_m[tid * 4 + 1];
        float m2 = sm_m[tid * 4 + 2], m3 = sm_m[tid * 4 + 3];
        float mg = fmaxf(fmaxf(m0v, m1), fmaxf(m2, m3));
        float Z = fexp(m0v - mg) * sm_s[tid * 4 + 0] + fexp(m1 - mg) * sm_s[tid * 4 + 1]
                + fexp(m2 - mg) * sm_s[tid * 4 + 2] + fexp(m3 - mg) * sm_s[tid * 4 + 3];
        size_t o = ((size_t)bz * 32 + blockIdx.x) * 4096 + m0 + tid;
        g_pm[o] = mg;
        g_ps[o] = Z;
    }
}

// combine 32 tile partials + border key -> m, 1/Z, bw
__global__ void sm_combine() {
    int i = blockIdx.x * 256 + threadIdx.x;
    int b = i >> 12, q = i & 4095;
    float sbv = g_sb[i];
    float mg = sbv;
#pragma unroll 8
    for (int t = 0; t < 32; t++)
        mg = fmaxf(mg, g_pm[((size_t)b * 32 + t) * 4096 + q]);
    float Z = 260.f * fexp(sbv - mg);
    float eb = Z;
#pragma unroll 8
    for (int t = 0; t < 32; t++) {
        size_t o = ((size_t)b * 32 + t) * 4096 + q;
        Z += fexp(g_pm[o] - mg) * g_ps[o];
    }
    float iz = 1.f / Z;
    g_m[i] = mg;
    g_iz[i] = iz;
    g_bw[i] = eb * iz;
}

// ---------------------------------------------------------------------------
// Fused O GEMM (fp16 single-term): out[c][q] = sum_k V[c][k]*p[k][q] + bw[q]*vbv[c]
// BM=256 (all c), BN=128 q, BK=32 keys. A: V fp16 cp.async 3-stage.
// B: LDG S fp32 -> exp*invZ -> fp16 -> STS double buffer.
// ---------------------------------------------------------------------------
#define OASTG (256*STR)                   // 20480 per A stage
#define OB0   (3*OASTG)                   // 61440
#define OBSTG (128*STR)                   // 10240 per B buffer
#define GSMEM_O (OB0 + 2*OBSTG)           // 81920

__global__ __launch_bounds__(256, 1) void gemm_o(float* __restrict__ Cout)
{
    extern __shared__ char sm_[];
    uint32_t smb = smem_u32(sm_);
    int tid = threadIdx.x, lane = tid & 31, wid = tid >> 5;
    int wm = wid >> 1, wn = wid & 1;
    int b = blockIdx.z;
    int n0 = blockIdx.x * 128;
    const __half* Vb = g_vf + (size_t)b * NC * NPIX;
    const int nk = 128;

    int brow = tid >> 1, half = tid & 1;
    int q = n0 + brow;
    float mq = g_m[b * 4096 + q];
    float izq = g_iz[b * 4096 + q];
    const float* Sg = g_S + ((size_t)b * 4096 + q) * 4096 + half * 16;

    auto loadA = [&](int kt) {
        int st = kt % 3;
#pragma unroll
        for (int u = 0; u < 4; u++) {
            int e = tid + u * 256;
            int row = e >> 2, ch = e & 3;
            cpa16(smb + st * OASTG + row * STR + ch * 16,
                  Vb + (size_t)row * 4096 + kt * 32 + ch * 8);
        }
        asm volatile("cp.async.commit_group;" ::: "memory");
    };

    float acc[4][8][4];
#pragma unroll
    for (int i = 0; i < 4; i++)
#pragma unroll
        for (int j = 0; j < 8; j++)
#pragma unroll
            for (int r = 0; r < 4; r++) acc[i][j][r] = 0.f;

    float4 f[4];
    loadA(0);
    loadA(1);
#pragma unroll
    for (int i = 0; i < 4; i++) f[i] = ((const float4*)Sg)[i];

    for (int kt = 0; kt < nk; kt++) {
        asm volatile("cp.async.wait_group 1;" ::: "memory");
        __syncthreads();
        // convert + STS B(kt)
        {
            float* fp = (float*)f;
            __half hh[16];
#pragma unroll
            for (int j = 0; j < 16; j++)
                hh[j] = __float2half(fexp(fp[j] - mq) * izq);
            int b2 = kt & 1;
            char* bp = sm_ + OB0 + b2 * OBSTG + brow * STR + half * 32;
            *(uint4*)bp = ((uint4*)hh)[0];
            *(uint4*)(bp + 16) = ((uint4*)hh)[1];
        }
        if (kt + 1 < nk) {
            const float4* s4 = (const float4*)(Sg + (kt + 1) * 32);
#pragma unroll
            for (int i = 0; i < 4; i++) f[i] = s4[i];
        }
        if (kt + 2 < nk) loadA(kt + 2);
        else asm volatile("cp.async.commit_group;" ::: "memory");
        __syncthreads();

        int st = kt % 3, b2 = kt & 1;
        uint32_t as_ = smb + st * OASTG + (wm * 64 + (lane & 15)) * STR + (lane >> 4) * 16;
        uint32_t bs_ = smb + OB0 + b2 * OBSTG + (wn * 64 + (lane & 15)) * STR + (lane >> 4) * 16;
#pragma unroll
        for (int kk = 0; kk < 2; kk++) {
            uint32_t a[4][4], bb[4][4];
#pragma unroll
            for (int mt = 0; mt < 4; mt++) ldm4(a[mt], as_ + mt * 16 * STR + kk * 32);
#pragma unroll
            for (int nt = 0; nt < 4; nt++) ldm4(bb[nt], bs_ + nt * 16 * STR + kk * 32);
#pragma unroll
            for (int mt = 0; mt < 4; mt++)
#pragma unroll
                for (int n8 = 0; n8 < 8; n8++)
                    mma16h(acc[mt][n8], a[mt], bb[n8 >> 1][n8 & 1], bb[n8 >> 1][(n8 & 1) + 2]);
        }
    }

    float* Cb = Cout + (size_t)b * NC * NPIX;
    const float* bwp = g_bw + (size_t)b * 4096;
#pragma unroll
    for (int mt = 0; mt < 4; mt++) {
        int row = wm * 64 + mt * 16 + (lane >> 2);
        float vb0 = g_vbv[row], vb1 = g_vbv[row + 8];
#pragma unroll
        for (int n8 = 0; n8 < 8; n8++) {
            int col = n0 + wn * 64 + n8 * 8 + (lane & 3) * 2;
            float w0 = bwp[col], w1 = bwp[col + 1];
            float2 v0, v1;
            v0.x = fmaf(w0, vb0, acc[mt][n8][0]); v0.y = fmaf(w1, vb0, acc[mt][n8][1]);
            v1.x = fmaf(w0, vb1, acc[mt][n8][2]); v1.y = fmaf(w1, vb1, acc[mt][n8][3]);
            *(float2*)&Cb[(size_t)row * 4096 + col] = v0;
            *(float2*)&Cb[(size_t)(row + 8) * 4096 + col] = v1;
        }
    }
}

// ---- prep kernels ----
__global__ void zero_k(uint4* p, int n) {
    int i = blockIdx.x * 256 + threadIdx.x;
    if (i < n) p[i] = make_uint4(0, 0, 0, 0);
}

__global__ void xt_fill(const float* __restrict__ x) {
    __shared__ float tile[32][33];
    int b = blockIdx.z;
    int p0 = blockIdx.x * 32, c0 = blockIdx.y * 32;
    int tx = threadIdx.x, ty = threadIdx.y;
    const float* s = x + (size_t)b * NC * NPIX;
    for (int j = 0; j < 32; j += 8)
        tile[ty + j][tx] = s[(size_t)(c0 + ty + j) * NPIX + p0 + tx];
    __syncthreads();
    for (int j = 0; j < 32; j += 8) {
        int p = p0 + ty + j, y = p >> 6, xx = p & 63;
        size_t o = ((size_t)b * 4356 + (y + 1) * 66 + (xx + 1)) * 256 + c0 + tx;
        __nv_bfloat16 h, l;
        split2(tile[tx][ty + j], h, l);
        g_xt_h[o] = h;
        g_xt_l[o] = l;
    }
}

__global__ void wsplit_q(const float* __restrict__ w) {
    int idx = blockIdx.x * 256 + threadIdx.x;
    if (idx >= NC * 2304) return;
    int m = idx / 2304, r = idx % 2304;
    int c = r / 9, t = r % 9;
    __nv_bfloat16 h, l;
    split2(w[idx], h, l);
    size_t base = (size_t)m * 6912 + t * 256 + c;
    g_wqh[base] = h; g_wqh[base + 2304] = h; g_wqh[base + 4608] = l;
}

__global__ void wsplit1(const float* __restrict__ w, __nv_bfloat16* __restrict__ o) {
    int idx = blockIdx.x * 256 + threadIdx.x;
    if (idx >= NC * NC) return;
    int m = idx / NC, c = idx % NC;
    __nv_bfloat16 h, l;
    split2(w[idx], h, l);
    size_t base = (size_t)m * 768 + c;
    o[base] = h; o[base + 256] = h; o[base + 512] = l;
}

__global__ void tsplit(const float* __restrict__ src, __nv_bfloat16* __restrict__ dst,
                       const float* __restrict__ aa, const float* __restrict__ ad, int patA) {
    __shared__ float tile[32][33];
    int b = blockIdx.z;
    int p0 = blockIdx.x * 32, c0 = blockIdx.y * 32;
    int tx = threadIdx.x, ty = threadIdx.y;
    const float* s = src + (size_t)b * NC * NPIX;
    for (int j = 0; j < 32; j += 8) {
        float a = aa[c0 + ty + j], d = ad[c0 + ty + j];
        tile[ty + j][tx] = fmaf(a, s[(size_t)(c0 + ty + j) * NPIX + p0 + tx], d);
    }
    __syncthreads();
    for (int j = 0; j < 32; j += 8) {
        __nv_bfloat16 h, l;
        split2(tile[tx][ty + j], h, l);
        __nv_bfloat16* o = dst + ((size_t)b * 4096 + p0 + ty + j) * 768 + c0 + tx;
        o[0] = h;
        o[256] = patA ? h : l;
        o[512] = patA ? l : h;
    }
}

// V affine -> fp16 [b][c][k]
__global__ void vf_k() {
    size_t i4 = (size_t)blockIdx.x * 256 + threadIdx.x;
    size_t e = i4 * 4;
    int c = (int)((e >> 12) & 255);
    float a = g_a[512 + c], d = g_dd[512 + c];
    float4 v = *(float4*)(g_vc + e);
    __half h[4];
    h[0] = __float2half(fmaf(a, v.x, d));
    h[1] = __float2half(fmaf(a, v.y, d));
    h[2] = __float2half(fmaf(a, v.z, d));
    h[3] = __float2half(fmaf(a, v.w, d));
    *(uint2*)(g_vf + e) = *(uint2*)h;
}

__global__ void stats_k(const float* __restrict__ bq, const float* __restrict__ gq, const float* __restrict__ betaq,
                        const float* __restrict__ bk, const float* __restrict__ gk, const float* __restrict__ betak,
                        const float* __restrict__ bv, const float* __restrict__ gv, const float* __restrict__ betav)
{
    int c = blockIdx.x, t = blockIdx.y;
    const float* src = (t == 0) ? g_qc : (t == 1) ? g_kc : g_vc;
    int tid = threadIdx.x;
    float s1 = 0.f, s2 = 0.f;
    for (int b = 0; b < NB; b++) {
        const float* p = src + ((size_t)b * NC + c) * NPIX;
        for (int i = tid; i < NPIX; i += 256) {
            float v = p[i];
            s1 += v; s2 += v * v;
        }
    }
    __shared__ double r1[256], r2[256];
    r1[tid] = s1; r2[tid] = s2;
    __syncthreads();
    for (int s = 128; s > 0; s >>= 1) {
        if (tid < s) { r1[tid] += r1[tid + s]; r2[tid] += r2[tid + s]; }
        __syncthreads();
    }
    if (tid == 0) {
        double S1 = r1[0], S2 = r2[0], cnt = 16384.0;
        float bias = (t == 0) ? bq[c] : (t == 1) ? bk[c] : bv[c];
        float g    = (t == 0) ? gq[c] : (t == 1) ? gk[c] : gv[c];
        float be   = (t == 0) ? betaq[c] : (t == 1) ? betak[c] : betav[c];
        if (t > 0) {
            cnt = 17424.0;
            S1 += 1040.0 * (double)bias;
            S2 += 1040.0 * (double)bias * (double)bias;
        }
        double mean = S1 / cnt;
        double var = S2 / cnt - mean * mean;
        float a = g * rsqrtf((float)var + 1e-5f);
        float d = be - a * (float)mean;
        g_a[t * NC + c] = a;
        g_dd[t * NC + c] = d;
        if (t == 1) g_kbv[c] = fmaf(a, bias, d);
        if (t == 2) g_vbv[c] = fmaf(a, bias, d);
    }
}

__global__ void sb_k() {
    int b = blockIdx.y;
    int q = blockIdx.x * 256 + threadIdx.x;
    const float* Q = g_qc + (size_t)b * NC * NPIX;
    float s = 0.f;
#pragma unroll 8
    for (int c = 0; c < NC; c++) {
        float qn = fmaf(g_a[c], Q[(size_t)c * NPIX + q], g_dd[c]);
        s = fmaf(g_kbv[c], qn, s);
    }
    g_sb[b * NPIX + q] = s;
}

// ---------------------------------------------------------------------------
extern "C" void kernel_launch(void* const* d_in, const int* in_sizes, int n_in,
                              void* d_out, int out_size)
{
    const float* x     = (const float*)d_in[0];
    const float* Wq    = (const float*)d_in[1];
    const float* bq    = (const float*)d_in[2];
    const float* gq    = (const float*)d_in[3];
    const float* betaq = (const float*)d_in[4];
    const float* Wk    = (const float*)d_in[5];
    const float* bk    = (const float*)d_in[6];
    const float* gk    = (const float*)d_in[7];
    const float* betak = (const float*)d_in[8];
    const float* Wv    = (const float*)d_in[9];
    const float* bv    = (const float*)d_in[10];
    const float* gv    = (const float*)d_in[11];
    const float* betav = (const float*)d_in[12];
    float* out = (float*)d_out;

    cudaFuncSetAttribute(gemm_conv<9>, cudaFuncAttributeMaxDynamicSharedMemorySize, GSMEM_C);
    cudaFuncSetAttribute(gemm_conv<1>, cudaFuncAttributeMaxDynamicSharedMemorySize, GSMEM_C);
    cudaFuncSetAttribute(gemm_s, cudaFuncAttributeMaxDynamicSharedMemorySize, GSMEM_S);
    cudaFuncSetAttribute(gemm_o, cudaFuncAttributeMaxDynamicSharedMemorySize, GSMEM_O);

    __nv_bfloat16 *p_xth, *p_xtl, *p_wqh, *p_wkh, *p_wvh, *p_qth, *p_kth;
    float *p_qc, *p_kc, *p_vc, *p_S, *p_a, *p_dd;
    cudaGetSymbolAddress((void**)&p_xth, g_xt_h);
    cudaGetSymbolAddress((void**)&p_xtl, g_xt_l);
    cudaGetSymbolAddress((void**)&p_wqh, g_wqh);
    cudaGetSymbolAddress((void**)&p_wkh, g_wkh);
    cudaGetSymbolAddress((void**)&p_wvh, g_wvh);
    cudaGetSymbolAddress((void**)&p_qth, g_qth);
    cudaGetSymbolAddress((void**)&p_kth, g_kth);
    cudaGetSymbolAddress((void**)&p_qc,  g_qc);
    cudaGetSymbolAddress((void**)&p_kc,  g_kc);
    cudaGetSymbolAddress((void**)&p_vc,  g_vc);
    cudaGetSymbolAddress((void**)&p_S,   g_S);
    cudaGetSymbolAddress((void**)&p_a,   g_a);
    cudaGetSymbolAddress((void**)&p_dd,  g_dd);

    // 1. padded transposed hi/lo x + weight splits
    int nz = (int)(((size_t)NB * 4356 * 256 * 2 / 16 + 255) / 256);
    zero_k<<<nz, 256>>>((uint4*)p_xth, (int)((size_t)NB * 4356 * 256 * 2 / 16));
    zero_k<<<nz, 256>>>((uint4*)p_xtl, (int)((size_t)NB * 4356 * 256 * 2 / 16));
    xt_fill<<<dim3(128, 8, NB), dim3(32, 8)>>>(x);
    wsplit_q<<<(NC * 2304 + 255) / 256, 256>>>(Wq);
    wsplit1<<<(NC * NC + 255) / 256, 256>>>(Wk, p_wkh);
    wsplit1<<<(NC * NC + 255) / 256, 256>>>(Wv, p_wvh);

    // 2. convs (implicit im2col, bf16x3)
    gemm_conv<9><<<dim3(32, 2, NB), 256, GSMEM_C>>>(p_wqh, p_qc, bq);
    gemm_conv<1><<<dim3(32, 2, NB), 256, GSMEM_C>>>(p_wkh, p_kc, bk);
    gemm_conv<1><<<dim3(32, 2, NB), 256, GSMEM_C>>>(p_wvh, p_vc, bv);

    // 3. BN stats + splits + border scores
    stats_k<<<dim3(256, 3), 256>>>(bq, gq, betaq, bk, gk, betak, bv, gv, betav);
    tsplit<<<dim3(128, 8, NB), dim3(32, 8)>>>(p_qc, p_qth, p_a, p_dd, 1);
    tsplit<<<dim3(128, 8, NB), dim3(32, 8)>>>(p_kc, p_kth, p_a + 256, p_dd + 256, 0);
    vf_k<<<(int)(((size_t)NB * NC * NPIX / 4) / 256), 256>>>();
    sb_k<<<dim3(16, NB), 256>>>();

    // 4. S[q][k] (bf16x3) + fused partial softmax stats
    gemm_s<<<dim3(32, 32, NB), 256, GSMEM_S>>>(p_qth, p_kth, p_S);

    // 5. combine partials -> m, 1/Z, bw
    sm_combine<<<64, 256>>>();

    // 6. fused O GEMM (fp16 single-term, exp in-kernel)
    gemm_o<<<dim3(32, 1, NB), 256, GSMEM_O>>>(out);
}

// round 9
// speedup vs baseline: 2.3013x; 1.0131x over previous
#include <cuda_runtime.h>
#include <cuda_bf16.h>
#include <cuda_fp16.h>
#include <math.h>
#include <stdint.h>

#define NB 4
#define NC 256
#define NPIX 4096
#define STR 80

// ---- static device scratch ----
__device__ __nv_bfloat16 g_xt_h[(size_t)NB*4356*256];   // padded x, [b][pix66][c] hi
__device__ __nv_bfloat16 g_xt_l[(size_t)NB*4356*256];   // lo
__device__ __nv_bfloat16 g_wqh[NC*6912];                // Wq split, A-pat [h,h,l]
__device__ __nv_bfloat16 g_wkh[NC*768];
__device__ __nv_bfloat16 g_wvh[NC*768];
__device__ float g_qc[(size_t)NB*NC*NPIX];
__device__ float g_kc[(size_t)NB*NC*NPIX];
__device__ float g_vc[(size_t)NB*NC*NPIX];
__device__ __nv_bfloat16 g_qth[(size_t)NB*NPIX*768];    // BN(Q)^T, A-pat
__device__ __nv_bfloat16 g_kth[(size_t)NB*NPIX*768];    // BN(K)^T, B-pat
__device__ __half g_vf[(size_t)NB*NC*NPIX];             // BN(V) fp16 [b][c][k]
__device__ __half g_P16[(size_t)NB*NPIX*NPIX];          // exp(s-lm) fp16 [b][q][k]
__device__ float g_pm[(size_t)NB*128*NPIX];             // per-32k-group max [b][g][q]
__device__ float g_ps[(size_t)NB*128*NPIX];             // per-32k-group sum [b][g][q]
__device__ float g_psum1[3*128*256];                    // conv partial sums  [t][slot][ch]
__device__ float g_psum2[3*128*256];                    // conv partial sumsq
__device__ float g_sb[NB*NPIX];
__device__ float g_bw[NB*NPIX];
__device__ float g_m[NB*NPIX];
__device__ float g_iz[NB*NPIX];
__device__ float g_a[3*NC];
__device__ float g_dd[3*NC];
__device__ float g_kbv[NC];
__device__ float g_vbv[NC];

// ---- helpers ----
__device__ __forceinline__ uint32_t smem_u32(const void* p) {
    uint32_t a;
    asm("{ .reg .u64 t; cvta.to.shared.u64 t, %1; cvt.u32.u64 %0, t; }" : "=r"(a) : "l"(p));
    return a;
}
__device__ __forceinline__ void cpa16(uint32_t s, const void* g) {
    asm volatile("cp.async.cg.shared.global [%0], [%1], 16;" :: "r"(s), "l"(g));
}
__device__ __forceinline__ void ldm4(uint32_t* r, uint32_t addr) {
    asm volatile("ldmatrix.sync.aligned.m8n8.x4.shared.b16 {%0,%1,%2,%3}, [%4];"
                 : "=r"(r[0]), "=r"(r[1]), "=r"(r[2]), "=r"(r[3]) : "r"(addr));
}
__device__ __forceinline__ void mma16(float* d, const uint32_t* a, uint32_t b0, uint32_t b1) {
    asm volatile(
        "mma.sync.aligned.m16n8k16.row.col.f32.bf16.bf16.f32 "
        "{%0,%1,%2,%3}, {%4,%5,%6,%7}, {%8,%9}, {%0,%1,%2,%3};"
        : "+f"(d[0]), "+f"(d[1]), "+f"(d[2]), "+f"(d[3])
        : "r"(a[0]), "r"(a[1]), "r"(a[2]), "r"(a[3]), "r"(b0), "r"(b1));
}
__device__ __forceinline__ void mma16h(float* d, const uint32_t* a, uint32_t b0, uint32_t b1) {
    asm volatile(
        "mma.sync.aligned.m16n8k16.row.col.f32.f16.f16.f32 "
        "{%0,%1,%2,%3}, {%4,%5,%6,%7}, {%8,%9}, {%0,%1,%2,%3};"
        : "+f"(d[0]), "+f"(d[1]), "+f"(d[2]), "+f"(d[3])
        : "r"(a[0]), "r"(a[1]), "r"(a[2]), "r"(a[3]), "r"(b0), "r"(b1));
}
__device__ __forceinline__ float fexp(float x) {
    x = fmaxf(x, -87.0f);
    float t = fmaf(x, 1.4426950408889634f, 12582912.0f);
    float i = t - 12582912.0f;
    float f = fmaf(x, 1.4426950408889634f, -i);
    float y = f * 0.6931471805599453f;
    float p = fmaf(y, 0.0083333338f, 0.041666668f);
    p = fmaf(y, p, 0.16666667f);
    p = fmaf(y, p, 0.5f);
    p = fmaf(y, p, 1.0f);
    p = fmaf(y, p, 1.0f);
    return p * __int_as_float(((int)i + 127) << 23);
}
__device__ __forceinline__ void split2(float v, __nv_bfloat16& h, __nv_bfloat16& l) {
    h = __float2bfloat16(v);
    l = __float2bfloat16(v - __bfloat162float(h));
}

// ---------------------------------------------------------------------------
// Implicit-im2col conv GEMM (bf16x3): BM=128, BN=128, BK=32, occ 2.
// Epilogue also emits per-channel (sum, sumsq) partials for fused BN stats.
// ---------------------------------------------------------------------------
#define CSTAGE (2*128*STR)
#define GSMEM_C (3*CSTAGE)

template <int TAPS>
__global__ __launch_bounds__(256, 2) void gemm_conv(
    const __nv_bfloat16* __restrict__ W, float* __restrict__ C,
    const float* __restrict__ bias, int ptype)
{
    extern __shared__ char sm_[];
    uint32_t smb = smem_u32(sm_);
    int tid = threadIdx.x, lane = tid & 31, wid = tid >> 5;
    int wm = wid & 1, wn = wid >> 1;
    int b = blockIdx.z;
    int m0 = blockIdx.y * 128, n0 = blockIdx.x * 128;
    const int Kp = TAPS * 768;
    const int nk = TAPS * 24;
    const __nv_bfloat16* XH = g_xt_h + (size_t)b * 4356 * 256;
    const __nv_bfloat16* XL = g_xt_l + (size_t)b * 4356 * 256;
    const __nv_bfloat16* Wb = W + (size_t)m0 * Kp;

    auto load = [&](int kt) {
        int st = kt % 3;
        uint32_t as = smb + st * CSTAGE;
        uint32_t bs = smb + st * CSTAGE + 128 * STR;
        int blk = kt / (TAPS * 8);
        int rem = kt - blk * (TAPS * 8);
        int t = rem >> 3, c0 = (rem & 7) << 5;
        int dy = (TAPS == 9) ? t / 3 : 1;
        int dx = (TAPS == 9) ? t % 3 : 1;
        const __nv_bfloat16* buf = (blk == 1) ? XL : XH;
#pragma unroll
        for (int u = 0; u < 2; u++) {
            int e = tid + u * 256;
            int row = e >> 2, ch = e & 3;
            cpa16(as + row * STR + ch * 16, Wb + (size_t)row * Kp + kt * 32 + ch * 8);
        }
#pragma unroll
        for (int u = 0; u < 2; u++) {
            int e = tid + u * 256;
            int row = e >> 2, ch = e & 3;
            int p = n0 + row, y = p >> 6, xx = p & 63;
            cpa16(bs + row * STR + ch * 16,
                  buf + (size_t)((y + dy) * 66 + (xx + dx)) * 256 + c0 + ch * 8);
        }
        asm volatile("cp.async.commit_group;" ::: "memory");
    };

    float acc[4][4][4];
#pragma unroll
    for (int i = 0; i < 4; i++)
#pragma unroll
        for (int j = 0; j < 4; j++)
#pragma unroll
            for (int r = 0; r < 4; r++) acc[i][j][r] = 0.f;

    load(0);
    load(1);
    for (int kt = 0; kt < nk; kt++) {
        asm volatile("cp.async.wait_group 1;" ::: "memory");
        __syncthreads();
        int st = kt % 3;
        uint32_t as = smb + st * CSTAGE + (wm * 64 + (lane & 15)) * STR + (lane >> 4) * 16;
        uint32_t bs = smb + st * CSTAGE + 128 * STR + (wn * 32 + (lane & 15)) * STR + (lane >> 4) * 16;
#pragma unroll
        for (int kk = 0; kk < 2; kk++) {
            uint32_t a[4][4], bb[2][4];
#pragma unroll
            for (int mt = 0; mt < 4; mt++) ldm4(a[mt], as + mt * 16 * STR + kk * 32);
#pragma unroll
            for (int nt = 0; nt < 2; nt++) ldm4(bb[nt], bs + nt * 16 * STR + kk * 32);
#pragma unroll
            for (int mt = 0; mt < 4; mt++)
#pragma unroll
                for (int n8 = 0; n8 < 4; n8++)
                    mma16(acc[mt][n8], a[mt], bb[n8 >> 1][n8 & 1], bb[n8 >> 1][(n8 & 1) + 2]);
        }
        __syncthreads();
        if (kt + 2 < nk) load(kt + 2);
        else asm volatile("cp.async.commit_group;" ::: "memory");
    }

    float* Cb = C + (size_t)b * NC * NPIX;
    float s1a[8], s2a[8];
#pragma unroll
    for (int i = 0; i < 8; i++) { s1a[i] = 0.f; s2a[i] = 0.f; }
#pragma unroll
    for (int mt = 0; mt < 4; mt++) {
        int row = m0 + wm * 64 + mt * 16 + (lane >> 2);
        float bi0 = bias[row], bi1 = bias[row + 8];
#pragma unroll
        for (int n8 = 0; n8 < 4; n8++) {
            int col = n0 + wn * 32 + n8 * 8 + (lane & 3) * 2;
            float2 v0, v1;
            v0.x = acc[mt][n8][0] + bi0; v0.y = acc[mt][n8][1] + bi0;
            v1.x = acc[mt][n8][2] + bi1; v1.y = acc[mt][n8][3] + bi1;
            *(float2*)&Cb[(size_t)row * 4096 + col] = v0;
            *(float2*)&Cb[(size_t)(row + 8) * 4096 + col] = v1;
            s1a[mt * 2 + 0] += v0.x + v0.y;
            s2a[mt * 2 + 0] += v0.x * v0.x + v0.y * v0.y;
            s1a[mt * 2 + 1] += v1.x + v1.y;
            s2a[mt * 2 + 1] += v1.x * v1.x + v1.y * v1.y;
        }
    }
    // reduce across lane&3 partners (same rows)
#pragma unroll
    for (int i = 0; i < 8; i++) {
        s1a[i] += __shfl_xor_sync(0xFFFFFFFF, s1a[i], 1);
        s1a[i] += __shfl_xor_sync(0xFFFFFFFF, s1a[i], 2);
        s2a[i] += __shfl_xor_sync(0xFFFFFFFF, s2a[i], 1);
        s2a[i] += __shfl_xor_sync(0xFFFFFFFF, s2a[i], 2);
    }
    __syncthreads();
    float* smr = (float*)sm_;              // [128][4] s1 | +2048B s2
    if ((lane & 3) == 0) {
#pragma unroll
        for (int mt = 0; mt < 4; mt++)
#pragma unroll
            for (int h = 0; h < 2; h++) {
                int r = wm * 64 + mt * 16 + h * 8 + (lane >> 2);
                smr[r * 4 + wn] = s1a[mt * 2 + h];
                smr[512 + r * 4 + wn] = s2a[mt * 2 + h];
            }
    }
    __syncthreads();
    if (tid < 128) {
        float a1 = smr[tid * 4] + smr[tid * 4 + 1] + smr[tid * 4 + 2] + smr[tid * 4 + 3];
        float a2 = smr[512 + tid * 4] + smr[512 + tid * 4 + 1]
                 + smr[512 + tid * 4 + 2] + smr[512 + tid * 4 + 3];
        int slot = b * 32 + blockIdx.x;
        g_psum1[(ptype * 128 + slot) * 256 + m0 + tid] = a1;
        g_psum2[(ptype * 128 + slot) * 256 + m0 + tid] = a2;
    }
}

// ---------------------------------------------------------------------------
// S GEMM (bf16x3): writes P16 = fp16(exp(s - lm)) + per-32k-group (max,sum).
// ---------------------------------------------------------------------------
#define SSTAGE (128*STR)
#define GSMEM_S (6*SSTAGE)

__global__ __launch_bounds__(256, 2) void gemm_s(
    const __nv_bfloat16* __restrict__ A, const __nv_bfloat16* __restrict__ B)
{
    extern __shared__ char sm_[];
    uint32_t smb = smem_u32(sm_);
    int tid = threadIdx.x, lane = tid & 31, wid = tid >> 5;
    int wm = wid & 1, wn = wid >> 1;
    int bz = blockIdx.z;
    int m0 = blockIdx.y * 128, n0 = blockIdx.x * 128;
    const __nv_bfloat16* Ab = A + (size_t)bz * 4096 * 768 + (size_t)m0 * 768;
    const __nv_bfloat16* Bb = B + (size_t)bz * 4096 * 768 + (size_t)n0 * 768;
    const int nk = 24;

    auto load = [&](int kt) {
        int st = kt % 3;
        uint32_t as = smb + st * SSTAGE;
        uint32_t bs = smb + 3 * SSTAGE + st * SSTAGE;
        int k0 = kt * 32;
#pragma unroll
        for (int i = 0; i < 2; i++) {
            int e = tid + i * 256;
            int row = e >> 2, ch = e & 3;
            cpa16(as + row * STR + ch * 16, Ab + (size_t)row * 768 + k0 + ch * 8);
            cpa16(bs + row * STR + ch * 16, Bb + (size_t)row * 768 + k0 + ch * 8);
        }
        asm volatile("cp.async.commit_group;" ::: "memory");
    };

    float acc[4][4][4];
#pragma unroll
    for (int i = 0; i < 4; i++)
#pragma unroll
        for (int j = 0; j < 4; j++)
#pragma unroll
            for (int r = 0; r < 4; r++) acc[i][j][r] = 0.f;

    load(0);
    load(1);
    for (int kt = 0; kt < nk; kt++) {
        asm volatile("cp.async.wait_group 1;" ::: "memory");
        __syncthreads();
        int st = kt % 3;
        uint32_t as = smb + st * SSTAGE + (wm * 64 + (lane & 15)) * STR + (lane >> 4) * 16;
        uint32_t bs = smb + 3 * SSTAGE + st * SSTAGE + (wn * 32 + (lane & 15)) * STR + (lane >> 4) * 16;
#pragma unroll
        for (int kk = 0; kk < 2; kk++) {
            uint32_t a[4][4], bb[2][4];
#pragma unroll
            for (int mt = 0; mt < 4; mt++) ldm4(a[mt], as + mt * 16 * STR + kk * 32);
#pragma unroll
            for (int nt = 0; nt < 2; nt++) ldm4(bb[nt], bs + nt * 16 * STR + kk * 32);
#pragma unroll
            for (int mt = 0; mt < 4; mt++)
#pragma unroll
                for (int n8 = 0; n8 < 4; n8++)
                    mma16(acc[mt][n8], a[mt], bb[n8 >> 1][n8 & 1], bb[n8 >> 1][(n8 & 1) + 2]);
        }
        __syncthreads();
        if (kt + 2 < nk) load(kt + 2);
        else asm volatile("cp.async.commit_group;" ::: "memory");
    }

    // epilogue: per-warp 32-k group max -> exp -> fp16 P, partial (m, sum)
    __half* Pb = g_P16 + (size_t)bz * 4096 * 4096;
    int g = blockIdx.x * 4 + wn;
#pragma unroll
    for (int mt = 0; mt < 4; mt++) {
#pragma unroll
        for (int h = 0; h < 2; h++) {
            float m = -3.4e38f;
#pragma unroll
            for (int n8 = 0; n8 < 4; n8++)
                m = fmaxf(m, fmaxf(acc[mt][n8][2 * h], acc[mt][n8][2 * h + 1]));
            m = fmaxf(m, __shfl_xor_sync(0xFFFFFFFF, m, 1));
            m = fmaxf(m, __shfl_xor_sync(0xFFFFFFFF, m, 2));
            int row = m0 + wm * 64 + mt * 16 + h * 8 + (lane >> 2);
            float s = 0.f;
#pragma unroll
            for (int n8 = 0; n8 < 4; n8++) {
                float e0 = fexp(acc[mt][n8][2 * h] - m);
                float e1 = fexp(acc[mt][n8][2 * h + 1] - m);
                s += e0 + e1;
                int col = n0 + wn * 32 + n8 * 8 + (lane & 3) * 2;
                *(__half2*)&Pb[(size_t)row * 4096 + col] = __floats2half2_rn(e0, e1);
            }
            s += __shfl_xor_sync(0xFFFFFFFF, s, 1);
            s += __shfl_xor_sync(0xFFFFFFFF, s, 2);
            if ((lane & 3) == 0) {
                size_t o = ((size_t)bz * 128 + g) * 4096 + row;
                g_pm[o] = m;
                g_ps[o] = s;
            }
        }
    }
}

// combine 128 group partials + border key -> m, 1/Z, bw
__global__ void sm_combine() {
    int i = blockIdx.x * 256 + threadIdx.x;
    int b = i >> 12, q = i & 4095;
    float sbv = g_sb[i];
    float mg = sbv;
#pragma unroll 8
    for (int t = 0; t < 128; t++)
        mg = fmaxf(mg, g_pm[((size_t)b * 128 + t) * 4096 + q]);
    float Z = 260.f * fexp(sbv - mg);
    float eb = Z;
#pragma unroll 8
    for (int t = 0; t < 128; t++) {
        size_t o = ((size_t)b * 128 + t) * 4096 + q;
        Z += fexp(g_pm[o] - mg) * g_ps[o];
    }
    float iz = 1.f / Z;
    g_m[i] = mg;
    g_iz[i] = iz;
    g_bw[i] = eb * iz;
}

// ---------------------------------------------------------------------------
// Fused O GEMM (fp16): out[c][q] = sum_k V[c][k]*p[k][q] + bw[q]*vbv[c]
// BM=256, BN=64 q, BK=32 keys, occ 2. B path: fp16 P * per-group scale.
// ---------------------------------------------------------------------------
#define OASTG (256*STR)                   // 20480 per A stage
#define OB0   (3*OASTG)                   // 61440
#define OBSTG (64*STR)                    // 5120 per B buffer
#define GSMEM_O (OB0 + 2*OBSTG)           // 71680

__global__ __launch_bounds__(256, 2) void gemm_o(float* __restrict__ Cout)
{
    extern __shared__ char sm_[];
    uint32_t smb = smem_u32(sm_);
    int tid = threadIdx.x, lane = tid & 31, wid = tid >> 5;
    int wm = wid >> 1, wn = wid & 1;
    int b = blockIdx.z;
    int n0 = blockIdx.x * 64;
    const __half* Vb = g_vf + (size_t)b * NC * NPIX;
    const int nk = 128;

    int fq = tid >> 2, fqt = tid & 3;      // fill role: q row, 8-half quarter
    int q = n0 + fq;
    float mq = g_m[b * 4096 + q];
    float izq = g_iz[b * 4096 + q];
    const __half* Pq = g_P16 + ((size_t)b * 4096 + q) * 4096 + fqt * 8;
    const float* pmq = g_pm + (size_t)b * 128 * 4096 + q;

    auto loadA = [&](int kt) {
        int st = kt % 3;
#pragma unroll
        for (int u = 0; u < 4; u++) {
            int e = tid + u * 256;
            int row = e >> 2, ch = e & 3;
            cpa16(smb + st * OASTG + row * STR + ch * 16,
                  Vb + (size_t)row * 4096 + kt * 32 + ch * 8);
        }
        asm volatile("cp.async.commit_group;" ::: "memory");
    };

    float acc[4][4][4];
#pragma unroll
    for (int i = 0; i < 4; i++)
#pragma unroll
        for (int j = 0; j < 4; j++)
#pragma unroll
            for (int r = 0; r < 4; r++) acc[i][j][r] = 0.f;

    uint4 pf;
    float pmv;
    loadA(0);
    loadA(1);
    pf = *(const uint4*)Pq;
    pmv = pmq[0];

    for (int kt = 0; kt < nk; kt++) {
        asm volatile("cp.async.wait_group 1;" ::: "memory");
        __syncthreads();
        // scale + STS B(kt)
        {
            float sc = fexp(pmv - mq) * izq;
            __half2 s2 = __float2half2_rn(sc);
            __half2* ph = (__half2*)&pf;
            uint4 o;
            __half2* oh = (__half2*)&o;
            oh[0] = __hmul2(ph[0], s2);
            oh[1] = __hmul2(ph[1], s2);
            oh[2] = __hmul2(ph[2], s2);
            oh[3] = __hmul2(ph[3], s2);
            *(uint4*)(sm_ + OB0 + (kt & 1) * OBSTG + fq * STR + fqt * 16) = o;
        }
        if (kt + 1 < nk) {
            pf = *(const uint4*)(Pq + (kt + 1) * 32);
            pmv = pmq[(size_t)(kt + 1) * 4096];
        }
        if (kt + 2 < nk) loadA(kt + 2);
        else asm volatile("cp.async.commit_group;" ::: "memory");
        __syncthreads();

        int st = kt % 3, b2 = kt & 1;
        uint32_t as_ = smb + st * OASTG + (wm * 64 + (lane & 15)) * STR + (lane >> 4) * 16;
        uint32_t bs_ = smb + OB0 + b2 * OBSTG + (wn * 32 + (lane & 15)) * STR + (lane >> 4) * 16;
#pragma unroll
        for (int kk = 0; kk < 2; kk++) {
            uint32_t a[4][4], bb[2][4];
#pragma unroll
            for (int mt = 0; mt < 4; mt++) ldm4(a[mt], as_ + mt * 16 * STR + kk * 32);
#pragma unroll
            for (int nt = 0; nt < 2; nt++) ldm4(bb[nt], bs_ + nt * 16 * STR + kk * 32);
#pragma unroll
            for (int mt = 0; mt < 4; mt++)
#pragma unroll
                for (int n8 = 0; n8 < 4; n8++)
                    mma16h(acc[mt][n8], a[mt], bb[n8 >> 1][n8 & 1], bb[n8 >> 1][(n8 & 1) + 2]);
        }
    }

    float* Cb = Cout + (size_t)b * NC * NPIX;
    const float* bwp = g_bw + (size_t)b * 4096;
#pragma unroll
    for (int mt = 0; mt < 4; mt++) {
        int row = wm * 64 + mt * 16 + (lane >> 2);
        float vb0 = g_vbv[row], vb1 = g_vbv[row + 8];
#pragma unroll
        for (int n8 = 0; n8 < 4; n8++) {
            int col = n0 + wn * 32 + n8 * 8 + (lane & 3) * 2;
            float w0 = bwp[col], w1 = bwp[col + 1];
            float2 v0, v1;
            v0.x = fmaf(w0, vb0, acc[mt][n8][0]); v0.y = fmaf(w1, vb0, acc[mt][n8][1]);
            v1.x = fmaf(w0, vb1, acc[mt][n8][2]); v1.y = fmaf(w1, vb1, acc[mt][n8][3]);
            *(float2*)&Cb[(size_t)row * 4096 + col] = v0;
            *(float2*)&Cb[(size_t)(row + 8) * 4096 + col] = v1;
        }
    }
}

// ---- prep kernels ----
__global__ void zero_k(uint4* p, int n) {
    int i = blockIdx.x * 256 + threadIdx.x;
    if (i < n) p[i] = make_uint4(0, 0, 0, 0);
}

__global__ void xt_fill(const float* __restrict__ x) {
    __shared__ float tile[32][33];
    int b = blockIdx.z;
    int p0 = blockIdx.x * 32, c0 = blockIdx.y * 32;
    int tx = threadIdx.x, ty = threadIdx.y;
    const float* s = x + (size_t)b * NC * NPIX;
    for (int j = 0; j < 32; j += 8)
        tile[ty + j][tx] = s[(size_t)(c0 + ty + j) * NPIX + p0 + tx];
    __syncthreads();
    for (int j = 0; j < 32; j += 8) {
        int p = p0 + ty + j, y = p >> 6, xx = p & 63;
        size_t o = ((size_t)b * 4356 + (y + 1) * 66 + (xx + 1)) * 256 + c0 + tx;
        __nv_bfloat16 h, l;
        split2(tile[tx][ty + j], h, l);
        g_xt_h[o] = h;
        g_xt_l[o] = l;
    }
}

__global__ void wsplit_q(const float* __restrict__ w) {
    int idx = blockIdx.x * 256 + threadIdx.x;
    if (idx >= NC * 2304) return;
    int m = idx / 2304, r = idx % 2304;
    int c = r / 9, t = r % 9;
    __nv_bfloat16 h, l;
    split2(w[idx], h, l);
    size_t base = (size_t)m * 6912 + t * 256 + c;
    g_wqh[base] = h; g_wqh[base + 2304] = h; g_wqh[base + 4608] = l;
}

__global__ void wsplit1(const float* __restrict__ w, __nv_bfloat16* __restrict__ o) {
    int idx = blockIdx.x * 256 + threadIdx.x;
    if (idx >= NC * NC) return;
    int m = idx / NC, c = idx % NC;
    __nv_bfloat16 h, l;
    split2(w[idx], h, l);
    size_t base = (size_t)m * 768 + c;
    o[base] = h; o[base + 256] = h; o[base + 512] = l;
}

__global__ void tsplit(const float* __restrict__ src, __nv_bfloat16* __restrict__ dst,
                       const float* __restrict__ aa, const float* __restrict__ ad, int patA) {
    __shared__ float tile[32][33];
    int b = blockIdx.z;
    int p0 = blockIdx.x * 32, c0 = blockIdx.y * 32;
    int tx = threadIdx.x, ty = threadIdx.y;
    const float* s = src + (size_t)b * NC * NPIX;
    for (int j = 0; j < 32; j += 8) {
        float a = aa[c0 + ty + j], d = ad[c0 + ty + j];
        tile[ty + j][tx] = fmaf(a, s[(size_t)(c0 + ty + j) * NPIX + p0 + tx], d);
    }
    __syncthreads();
    for (int j = 0; j < 32; j += 8) {
        __nv_bfloat16 h, l;
        split2(tile[tx][ty + j], h, l);
        __nv_bfloat16* o = dst + ((size_t)b * 4096 + p0 + ty + j) * 768 + c0 + tx;
        o[0] = h;
        o[256] = patA ? h : l;
        o[512] = patA ? l : h;
    }
}

__global__ void vf_k() {
    size_t i4 = (size_t)blockIdx.x * 256 + threadIdx.x;
    size_t e = i4 * 4;
    int c = (int)((e >> 12) & 255);
    float a = g_a[512 + c], d = g_dd[512 + c];
    float4 v = *(float4*)(g_vc + e);
    __half h[4];
    h[0] = __float2half(fmaf(a, v.x, d));
    h[1] = __float2half(fmaf(a, v.y, d));
    h[2] = __float2half(fmaf(a, v.z, d));
    h[3] = __float2half(fmaf(a, v.w, d));
    *(uint2*)(g_vf + e) = *(uint2*)h;
}

// tiny stats: sum 128 conv partials per channel
__global__ void stats_k(const float* __restrict__ bq, const float* __restrict__ gq, const float* __restrict__ betaq,
                        const float* __restrict__ bk, const float* __restrict__ gk, const float* __restrict__ betak,
                        const float* __restrict__ bv, const float* __restrict__ gv, const float* __restrict__ betav)
{
    int t = blockIdx.x;    // 0:Q 1:K 2:V
    int c = threadIdx.x;   // 0..255
    float S1f = 0.f, S2f = 0.f;
    for (int j = 0; j < 128; j++) {
        S1f += g_psum1[(t * 128 + j) * 256 + c];
        S2f += g_psum2[(t * 128 + j) * 256 + c];
    }
    double S1 = S1f, S2 = S2f, cnt = 16384.0;
    float bias = (t == 0) ? bq[c] : (t == 1) ? bk[c] : bv[c];
    float g    = (t == 0) ? gq[c] : (t == 1) ? gk[c] : gv[c];
    float be   = (t == 0) ? betaq[c] : (t == 1) ? betak[c] : betav[c];
    if (t > 0) {
        cnt = 17424.0;
        S1 += 1040.0 * (double)bias;
        S2 += 1040.0 * (double)bias * (double)bias;
    }
    double mean = S1 / cnt;
    double var = S2 / cnt - mean * mean;
    float a = g * rsqrtf((float)var + 1e-5f);
    float d = be - a * (float)mean;
    g_a[t * NC + c] = a;
    g_dd[t * NC + c] = d;
    if (t == 1) g_kbv[c] = fmaf(a, bias, d);
    if (t == 2) g_vbv[c] = fmaf(a, bias, d);
}

__global__ void sb_k() {
    int b = blockIdx.y;
    int q = blockIdx.x * 256 + threadIdx.x;
    const float* Q = g_qc + (size_t)b * NC * NPIX;
    float s = 0.f;
#pragma unroll 8
    for (int c = 0; c < NC; c++) {
        float qn = fmaf(g_a[c], Q[(size_t)c * NPIX + q], g_dd[c]);
        s = fmaf(g_kbv[c], qn, s);
    }
    g_sb[b * NPIX + q] = s;
}

// ---------------------------------------------------------------------------
extern "C" void kernel_launch(void* const* d_in, const int* in_sizes, int n_in,
                              void* d_out, int out_size)
{
    const float* x     = (const float*)d_in[0];
    const float* Wq    = (const float*)d_in[1];
    const float* bq    = (const float*)d_in[2];
    const float* gq    = (const float*)d_in[3];
    const float* betaq = (const float*)d_in[4];
    const float* Wk    = (const float*)d_in[5];
    const float* bk    = (const float*)d_in[6];
    const float* gk    = (const float*)d_in[7];
    const float* betak = (const float*)d_in[8];
    const float* Wv    = (const float*)d_in[9];
    const float* bv    = (const float*)d_in[10];
    const float* gv    = (const float*)d_in[11];
    const float* betav = (const float*)d_in[12];
    float* out = (float*)d_out;

    cudaFuncSetAttribute(gemm_conv<9>, cudaFuncAttributeMaxDynamicSharedMemorySize, GSMEM_C);
    cudaFuncSetAttribute(gemm_conv<1>, cudaFuncAttributeMaxDynamicSharedMemorySize, GSMEM_C);
    cudaFuncSetAttribute(gemm_s, cudaFuncAttributeMaxDynamicSharedMemorySize, GSMEM_S);
    cudaFuncSetAttribute(gemm_o, cudaFuncAttributeMaxDynamicSharedMemorySize, GSMEM_O);

    __nv_bfloat16 *p_xth, *p_xtl, *p_wqh, *p_wkh, *p_wvh, *p_qth, *p_kth;
    float *p_qc, *p_kc, *p_vc, *p_a, *p_dd;
    cudaGetSymbolAddress((void**)&p_xth, g_xt_h);
    cudaGetSymbolAddress((void**)&p_xtl, g_xt_l);
    cudaGetSymbolAddress((void**)&p_wqh, g_wqh);
    cudaGetSymbolAddress((void**)&p_wkh, g_wkh);
    cudaGetSymbolAddress((void**)&p_wvh, g_wvh);
    cudaGetSymbolAddress((void**)&p_qth, g_qth);
    cudaGetSymbolAddress((void**)&p_kth, g_kth);
    cudaGetSymbolAddress((void**)&p_qc,  g_qc);
    cudaGetSymbolAddress((void**)&p_kc,  g_kc);
    cudaGetSymbolAddress((void**)&p_vc,  g_vc);
    cudaGetSymbolAddress((void**)&p_a,   g_a);
    cudaGetSymbolAddress((void**)&p_dd,  g_dd);

    // 1. padded transposed hi/lo x + weight splits
    int nz = (int)(((size_t)NB * 4356 * 256 * 2 / 16 + 255) / 256);
    zero_k<<<nz, 256>>>((uint4*)p_xth, (int)((size_t)NB * 4356 * 256 * 2 / 16));
    zero_k<<<nz, 256>>>((uint4*)p_xtl, (int)((size_t)NB * 4356 * 256 * 2 / 16));
    xt_fill<<<dim3(128, 8, NB), dim3(32, 8)>>>(x);
    wsplit_q<<<(NC * 2304 + 255) / 256, 256>>>(Wq);
    wsplit1<<<(NC * NC + 255) / 256, 256>>>(Wk, p_wkh);
    wsplit1<<<(NC * NC + 255) / 256, 256>>>(Wv, p_wvh);

    // 2. convs (implicit im2col, bf16x3, fused stat partials)
    gemm_conv<9><<<dim3(32, 2, NB), 256, GSMEM_C>>>(p_wqh, p_qc, bq, 0);
    gemm_conv<1><<<dim3(32, 2, NB), 256, GSMEM_C>>>(p_wkh, p_kc, bk, 1);
    gemm_conv<1><<<dim3(32, 2, NB), 256, GSMEM_C>>>(p_wvh, p_vc, bv, 2);

    // 3. BN stats (tiny) + splits + border scores
    stats_k<<<3, 256>>>(bq, gq, betaq, bk, gk, betak, bv, gv, betav);
    tsplit<<<dim3(128, 8, NB), dim3(32, 8)>>>(p_qc, p_qth, p_a, p_dd, 1);
    tsplit<<<dim3(128, 8, NB), dim3(32, 8)>>>(p_kc, p_kth, p_a + 256, p_dd + 256, 0);
    vf_k<<<(int)(((size_t)NB * NC * NPIX / 4) / 256), 256>>>();
    sb_k<<<dim3(16, NB), 256>>>();

    // 4. S GEMM -> fp16 exp-tiles + group partials
    gemm_s<<<dim3(32, 32, NB), 256, GSMEM_S>>>(p_qth, p_kth);

    // 5. combine partials -> m, 1/Z, bw
    sm_combine<<<64, 256>>>();

    // 6. fused O GEMM (fp16, occ 2)
    gemm_o<<<dim3(64, 1, NB), 256, GSMEM_O>>>(out);
}